// round 13
// baseline (speedup 1.0000x reference)
#include <cuda_runtime.h>
#include <cuda_fp16.h>
#include <math.h>

#define B_   8
#define C_   16
#define D_   64
#define HW_  64
#define NP_  64
#define IMG_ 128

typedef unsigned long long ull;

// ---------------- f32x2 helpers (sm_10x packed fp32 FMA) ----------------
__device__ __forceinline__ ull pk2(float x, float y) {
    ull r;
    asm("mov.b64 %0, {%1, %2};" : "=l"(r) : "f"(x), "f"(y));
    return r;
}
__device__ __forceinline__ void fma2(ull& d, ull a, ull b) {
    asm("fma.rn.f32x2 %0, %1, %2, %0;" : "+l"(d) : "l"(a), "l"(b));
}
__device__ __forceinline__ float2 unpk(ull v) {
    float2 r;
    asm("mov.b64 {%0, %1}, %2;" : "=f"(r.x), "=f"(r.y) : "l"(v));
    return r;
}

// ---------------- device scratch (static, allocation-free) ----------------
__device__ __align__(16) __half g_featT[(size_t)B_ * D_ * D_ * D_ * C_];
__device__ __align__(16) float  g_imgs[B_ * C_ * HW_ * HW_];
__device__ __align__(16) float  g_opac[B_ * HW_ * HW_];
__device__ __align__(16) float  g_x1[B_ * 16 * IMG_ * IMG_];
__device__ __align__(16) float  g_x2[B_ * 8  * IMG_ * IMG_];
__device__ double g_sum1[16], g_sq1[16];
__device__ double g_sum2[8],  g_sq2[8];

// ---------------- feature transpose: (B,16,D,D,D) -> (B,D^3,16) fp16; clears stats (R8) ----------------
__global__ void k_transpose(const float* __restrict__ f) {
    if (blockIdx.x == 0 && threadIdx.x < 16) {
        g_sum1[threadIdx.x] = 0.0; g_sq1[threadIdx.x] = 0.0;
        if (threadIdx.x < 8) { g_sum2[threadIdx.x] = 0.0; g_sq2[threadIdx.x] = 0.0; }
    }
    int idx = blockIdx.x * blockDim.x + threadIdx.x;
    if (idx >= B_ * D_ * D_ * D_) return;
    int b = idx >> 18;
    int v = idx & 262143;
    __align__(16) __half2 tmp[8];
#pragma unroll
    for (int c = 0; c < 8; c++) {
        float a = f[((size_t)(b * 16 + 2 * c)) * 262144 + v];
        float bb = f[((size_t)(b * 16 + 2 * c + 1)) * 262144 + v];
        tmp[c] = __floats2half2_rn(a, bb);
    }
    uint4* out = reinterpret_cast<uint4*>(g_featT + (size_t)idx * 16);
    out[0] = *reinterpret_cast<uint4*>(&tmp[0]);
    out[1] = *reinterpret_cast<uint4*>(&tmp[4]);
}

// ---------------- trilerp corner helper: clamped offsets, masked weights ----------------
__device__ __forceinline__ void make_corners(float ix, float iy, float iz,
                                             float* __restrict__ ws, int* __restrict__ off) {
    float xf = floorf(ix), yf = floorf(iy), zf = floorf(iz);
    float fx = ix - xf, fy = iy - yf, fz = iz - zf;
    int x0 = (int)xf, y0 = (int)yf, z0 = (int)zf;
    float wx[2] = {1.0f - fx, fx};
    float wy[2] = {1.0f - fy, fy};
    float wz[2] = {1.0f - fz, fz};
#pragma unroll
    for (int k = 0; k < 8; k++) {
        int dx = k & 1, dy = (k >> 1) & 1, dz = k >> 2;
        int xc = x0 + dx, yc = y0 + dy, zc = z0 + dz;
        bool v = ((unsigned)xc < 64u) && ((unsigned)yc < 64u) && ((unsigned)zc < 64u);
        ws[k] = v ? wx[dx] * wy[dy] * wz[dz] : 0.0f;
        int o = (zc * 64 + yc) * 64 + xc;
        off[k] = min(max(o, 0), 262143);
    }
}

__device__ __forceinline__ void acc_rec(float wk, uint4 r0, uint4 r1, float* __restrict__ acc) {
    float2 v;
    v = __half22float2(*reinterpret_cast<const __half2*>(&r0.x));
    acc[0]  = fmaf(wk, v.x, acc[0]);  acc[1]  = fmaf(wk, v.y, acc[1]);
    v = __half22float2(*reinterpret_cast<const __half2*>(&r0.y));
    acc[2]  = fmaf(wk, v.x, acc[2]);  acc[3]  = fmaf(wk, v.y, acc[3]);
    v = __half22float2(*reinterpret_cast<const __half2*>(&r0.z));
    acc[4]  = fmaf(wk, v.x, acc[4]);  acc[5]  = fmaf(wk, v.y, acc[5]);
    v = __half22float2(*reinterpret_cast<const __half2*>(&r0.w));
    acc[6]  = fmaf(wk, v.x, acc[6]);  acc[7]  = fmaf(wk, v.y, acc[7]);
    v = __half22float2(*reinterpret_cast<const __half2*>(&r1.x));
    acc[8]  = fmaf(wk, v.x, acc[8]);  acc[9]  = fmaf(wk, v.y, acc[9]);
    v = __half22float2(*reinterpret_cast<const __half2*>(&r1.y));
    acc[10] = fmaf(wk, v.x, acc[10]); acc[11] = fmaf(wk, v.y, acc[11]);
    v = __half22float2(*reinterpret_cast<const __half2*>(&r1.z));
    acc[12] = fmaf(wk, v.x, acc[12]); acc[13] = fmaf(wk, v.y, acc[13]);
    v = __half22float2(*reinterpret_cast<const __half2*>(&r1.w));
    acc[14] = fmaf(wk, v.x, acc[14]); acc[15] = fmaf(wk, v.y, acc[15]);
}

// ---------------- fused ray-march: 8 threads per pixel (8 depths each) ----------------
__global__ void k_render(const float* __restrict__ R, const float* __restrict__ T,
                         const float* __restrict__ K, const float* __restrict__ dens) {
    int gid = blockIdx.x * 128 + threadIdx.x;
    int seg = gid & 7;
    int pix = gid >> 3;
    int b = pix >> 12;
    int h = (pix >> 6) & 63;
    int w = pix & 63;

    const float* Rb = R + b * 9;
    const float* Kb = K + b * 9;
    const float* Tb = T + b * 3;

    float fxk = Kb[0] * 0.5f, cxk = Kb[2] * 0.5f;
    float fyk = Kb[4] * 0.5f, cyk = Kb[5] * 0.5f;
    float dcx = ((float)w + 0.5f - cxk) / fxk;
    float dcy = ((float)h + 0.5f - cyk) / fyk;

    float dwx = Rb[0] * dcx + Rb[3] * dcy + Rb[6];
    float dwy = Rb[1] * dcx + Rb[4] * dcy + Rb[7];
    float dwz = Rb[2] * dcx + Rb[5] * dcy + Rb[8];
    float ox = -(Rb[0] * Tb[0] + Rb[3] * Tb[1] + Rb[6] * Tb[2]);
    float oy = -(Rb[1] * Tb[0] + Rb[4] * Tb[1] + Rb[7] * Tb[2]);
    float oz = -(Rb[2] * Tb[0] + Rb[5] * Tb[1] + Rb[8] * Tb[2]);

    const float scale = 2.0f / ((1.0f / (float)D_) * (float)(D_ - 1));
    const float sgain = scale * 31.5f;
    const float dstep = (2.8f - 1.2f) / 63.0f;

    const float* db = dens + (size_t)b * 262144;
    const uint4* fb = reinterpret_cast<const uint4*>(g_featT) + (size_t)b * 262144 * 2;

    // ---- Phase A: segment-local transmittance products ----
    float Lea = 1.0f, Lpq = 1.0f;
#pragma unroll
    for (int j = 0; j < 8; j++) {
        int p = seg * 8 + j;
        float dpt = 1.2f + (float)p * dstep;
        float ix = fmaf(ox + dwx * dpt, sgain, 31.5f);
        float iy = fmaf(oy + dwy * dpt, sgain, 31.5f);
        float iz = fmaf(oz + dwz * dpt, sgain, 31.5f);
        float ws[8]; int off[8];
        make_corners(ix, iy, iz, ws, off);
        float d[8];
#pragma unroll
        for (int k = 0; k < 8; k++) d[k] = __ldg(&db[off[k]]);
        float s = 0.0f;
#pragma unroll
        for (int k = 0; k < 8; k++) s = fmaf(ws[k], d[k], s);
        Lea *= (1.0f + 1e-10f - s);
        Lpq *= (1.0f - s);
    }

    // ---- Phase B: exclusive scan across the 8-lane group ----
    float ex = __shfl_up_sync(0xffffffffu, Lea, 1);
    ex = (seg == 0) ? 1.0f : ex;
    float u = __shfl_up_sync(0xffffffffu, ex, 1);
    if (seg >= 1) ex *= u;
    u = __shfl_up_sync(0xffffffffu, ex, 2);
    if (seg >= 2) ex *= u;
    u = __shfl_up_sync(0xffffffffu, ex, 4);
    if (seg >= 4) ex *= u;
    float pq = Lpq;
    pq *= __shfl_xor_sync(0xffffffffu, pq, 1);
    pq *= __shfl_xor_sync(0xffffffffu, pq, 2);
    pq *= __shfl_xor_sync(0xffffffffu, pq, 4);

    // ---- Phase C: weighted feature gathers ----
    float acc[16];
#pragma unroll
    for (int c = 0; c < 16; c++) acc[c] = 0.0f;
    float Tcur = ex;
    for (int j = 0; j < 8; j++) {
        int p = seg * 8 + j;
        float dpt = 1.2f + (float)p * dstep;
        float ix = fmaf(ox + dwx * dpt, sgain, 31.5f);
        float iy = fmaf(oy + dwy * dpt, sgain, 31.5f);
        float iz = fmaf(oz + dwz * dpt, sgain, 31.5f);
        float ws[8]; int off[8];
        make_corners(ix, iy, iz, ws, off);
        float d[8];
#pragma unroll
        for (int k = 0; k < 8; k++) d[k] = __ldg(&db[off[k]]);
        float s = 0.0f;
#pragma unroll
        for (int k = 0; k < 8; k++) s = fmaf(ws[k], d[k], s);
        float wq = s * Tcur;
        Tcur *= (1.0f + 1e-10f - s);
        if (wq == 0.0f) continue;

        uint4 a0[4], a1[4];
#pragma unroll
        for (int k = 0; k < 4; k++) {
            const uint4* rec = fb + ((size_t)off[k] << 1);
            a0[k] = __ldg(rec);
            a1[k] = __ldg(rec + 1);
        }
#pragma unroll
        for (int k = 0; k < 4; k++) acc_rec(wq * ws[k], a0[k], a1[k], acc);
#pragma unroll
        for (int k = 0; k < 4; k++) {
            const uint4* rec = fb + ((size_t)off[k + 4] << 1);
            a0[k] = __ldg(rec);
            a1[k] = __ldg(rec + 1);
        }
#pragma unroll
        for (int k = 0; k < 4; k++) acc_rec(wq * ws[k + 4], a0[k], a1[k], acc);
    }

    // ---- Phase D: reduce across the 8-lane group ----
#pragma unroll
    for (int c = 0; c < 16; c++) {
        acc[c] += __shfl_xor_sync(0xffffffffu, acc[c], 1);
        acc[c] += __shfl_xor_sync(0xffffffffu, acc[c], 2);
        acc[c] += __shfl_xor_sync(0xffffffffu, acc[c], 4);
    }
    if (seg == 0) {
#pragma unroll
        for (int c = 0; c < 16; c++)
            g_imgs[((b * 16 + c) << 12) + (h << 6) + w] = acc[c];
        g_opac[pix] = 1.0f - pq;
    }
}

// ---------------- transposed conv 6x6 s2, f32x2, 2 same-parity X per thread + BN1 stats (R8) ----------------
__global__ void k_convt(const float* __restrict__ wt, const float* __restrict__ bt) {
    __shared__ __align__(16) ull swt[16 * 18 * 8];
    __shared__ __align__(16) float tile[8][7][68];
    __shared__ float rsum[8][16], rsq[8][16];
    int tx = threadIdx.x, ty = threadIdx.y;
    int t = ty * 32 + tx;
    int px = blockIdx.x;
    int kx0 = (px + 1) & 1;

    for (int j = t; j < 2304; j += 256) {
        int p = j & 7;
        int tap = (j >> 3) % 18;
        int i = j / 144;
        int ky = tap / 3, kxi = tap % 3;
        int kx = kx0 + 2 * kxi;
        int base = (i * 16 + 2 * p) * 36 + (5 - ky) * 6 + (5 - kx);
        swt[j] = pk2(wt[base], wt[base + 36]);
    }

    int Y0 = blockIdx.y * 8, b = blockIdx.z;
    int Y = Y0 + ty;
    int Xa = 4 * tx + px;
    int Xb = Xa + 2;
    int mb = (Y0 >> 1) - 2;
    int ky0 = (Y + 1) & 1;

    ull accA[8], accB[8];
#pragma unroll
    for (int p = 0; p < 8; p++) {
        ull iv = pk2(bt[2 * p], bt[2 * p + 1]);
        accA[p] = iv; accB[p] = iv;
    }

    for (int cc = 0; cc < 2; cc++) {
        __syncthreads();
        for (int j = t; j < 3808; j += 256) {
            int il = j / 476;
            int rem = j % 476;
            int r = rem / 68;
            int n = rem % 68;
            int mm = mb + r, nn = n - 1;
            float v = 0.0f;
            if ((unsigned)mm < 64u && (unsigned)nn < 64u)
                v = g_imgs[((b * 16 + cc * 8 + il) * 64 + mm) * 64 + nn];
            tile[il][r][n] = v;
        }
        __syncthreads();

#pragma unroll
        for (int kk = 0; kk < 3; kk++) {
            int ky = ky0 + 2 * kk;
            int tr = ((Y + ky - 3) >> 1) - mb;
#pragma unroll
            for (int kxi = 0; kxi < 3; kxi++) {
                int kx = kx0 + 2 * kxi;
                int tca = ((Xa + kx - 3) >> 1) + 1;
#pragma unroll
                for (int il = 0; il < 8; il++) {
                    int i = cc * 8 + il;
                    float va = tile[il][tr][tca];
                    float vb = tile[il][tr][tca + 1];
                    ull pa = pk2(va, va), pb = pk2(vb, vb);
                    const ulonglong2* wp = reinterpret_cast<const ulonglong2*>(&swt[(i * 18 + ky * 3 + kxi) * 8]);
                    ulonglong2 q0 = wp[0], q1 = wp[1], q2 = wp[2], q3 = wp[3];
                    fma2(accA[0], q0.x, pa); fma2(accB[0], q0.x, pb);
                    fma2(accA[1], q0.y, pa); fma2(accB[1], q0.y, pb);
                    fma2(accA[2], q1.x, pa); fma2(accB[2], q1.x, pb);
                    fma2(accA[3], q1.y, pa); fma2(accB[3], q1.y, pb);
                    fma2(accA[4], q2.x, pa); fma2(accB[4], q2.x, pb);
                    fma2(accA[5], q2.y, pa); fma2(accB[5], q2.y, pb);
                    fma2(accA[6], q3.x, pa); fma2(accB[6], q3.x, pb);
                    fma2(accA[7], q3.y, pa); fma2(accB[7], q3.y, pb);
                }
            }
        }
    }

    float so[16], sq[16];
#pragma unroll
    for (int p = 0; p < 8; p++) {
        float2 a = unpk(accA[p]);
        float2 bb = unpk(accB[p]);
        int o0 = 2 * p, o1 = 2 * p + 1;
        g_x1[((b * 16 + o0) * 128 + Y) * 128 + Xa] = a.x;
        g_x1[((b * 16 + o0) * 128 + Y) * 128 + Xb] = bb.x;
        g_x1[((b * 16 + o1) * 128 + Y) * 128 + Xa] = a.y;
        g_x1[((b * 16 + o1) * 128 + Y) * 128 + Xb] = bb.y;
        so[o0] = a.x + bb.x;           sq[o0] = a.x * a.x + bb.x * bb.x;
        so[o1] = a.y + bb.y;           sq[o1] = a.y * a.y + bb.y * bb.y;
    }
#pragma unroll
    for (int c = 0; c < 16; c++) {
        float s = so[c], q = sq[c];
#pragma unroll
        for (int d = 16; d > 0; d >>= 1) {
            s += __shfl_xor_sync(0xffffffffu, s, d);
            q += __shfl_xor_sync(0xffffffffu, q, d);
        }
        if (tx == 0) { rsum[ty][c] = s; rsq[ty][c] = q; }
    }
    __syncthreads();
    if (t < 16) {
        float S = 0.0f, Q = 0.0f;
#pragma unroll
        for (int wq = 0; wq < 8; wq++) { S += rsum[wq][t]; Q += rsq[wq][t]; }
        atomicAdd(&g_sum1[t], (double)S);
        atomicAdd(&g_sq1[t],  (double)Q);
    }
}

// ---------------- conv1 5x5 pad2: out-channel split, 512 CTAs x (32,4,2) (R8) ----------------
__global__ void k_conv1(const float* __restrict__ w1, const float* __restrict__ b1,
                        const float* __restrict__ g1, const float* __restrict__ be1) {
    __shared__ __align__(16) ull swp[16 * 25 * 4];
    __shared__ __align__(16) float tile[16][8][68];
    __shared__ float rsum[8][4], rsq[8][4];
    __shared__ float sa[16], sc[16];
    int tx = threadIdx.x, ty = threadIdx.y, tz = threadIdx.z;
    int t = tz * 128 + ty * 32 + tx;

    for (int j = t; j < 1600; j += 256) {
        int p = j & 3;
        int tap = (j >> 2) % 25;
        int i = j / 100;
        swp[(i * 25 + tap) * 4 + p] = pk2(w1[(2 * p) * 400 + i * 25 + tap],
                                          w1[(2 * p + 1) * 400 + i * 25 + tap]);
    }
    if (t < 16) {
        double N = (double)(B_ * IMG_ * IMG_);
        double m = g_sum1[t] / N;
        double v = g_sq1[t] / N - m * m;
        float rs = rsqrtf((float)v + 1e-5f);
        float a = g1[t] * rs;
        sa[t] = a;
        sc[t] = be1[t] - (float)m * a;
    }
    __syncthreads();

    int Xb = blockIdx.x * 64;
    int Y0 = blockIdx.y * 4, b = blockIdx.z;
    int Y = Y0 + ty;
    int X = Xb + 2 * tx;

    for (int j = t; j < 8704; j += 256) {
        int il = j / 544;
        int rem = j % 544;
        int r = rem / 68;
        int n = rem % 68;
        int yy = Y0 - 2 + r, xx = Xb - 2 + n;
        float v = 0.0f;
        if ((unsigned)yy < 128u && (unsigned)xx < 128u) {
            float xv = g_x1[((b * 16 + il) * 128 + yy) * 128 + xx];
            xv = sa[il] * xv + sc[il];
            v = (xv >= 0.0f) ? xv : 0.01f * xv;
        }
        tile[il][r][n] = v;
    }
    __syncthreads();

    ull acc[2][2];
    {
        ull iv0 = pk2(b1[4 * tz], b1[4 * tz + 1]);
        ull iv1 = pk2(b1[4 * tz + 2], b1[4 * tz + 3]);
        acc[0][0] = iv0; acc[1][0] = iv0;
        acc[0][1] = iv1; acc[1][1] = iv1;
    }

#pragma unroll
    for (int i = 0; i < 16; i++) {
#pragma unroll
        for (int ky = 0; ky < 5; ky++) {
            const float2* rp = reinterpret_cast<const float2*>(&tile[i][ty + ky][tx * 2]);
            float2 a0 = rp[0], a1 = rp[1], a2 = rp[2];
            float w6[6] = {a0.x, a0.y, a1.x, a1.y, a2.x, a2.y};
            ull pw[6];
#pragma unroll
            for (int j2 = 0; j2 < 6; j2++) pw[j2] = pk2(w6[j2], w6[j2]);
#pragma unroll
            for (int kx = 0; kx < 5; kx++) {
                const ulonglong2* wp = reinterpret_cast<const ulonglong2*>(&swp[(i * 25 + ky * 5 + kx) * 4 + 2 * tz]);
                ulonglong2 wv = *wp;
                ull v0 = pw[kx], v1 = pw[kx + 1];
                fma2(acc[0][0], wv.x, v0); fma2(acc[1][0], wv.x, v1);
                fma2(acc[0][1], wv.y, v0); fma2(acc[1][1], wv.y, v1);
            }
        }
    }

    float so[4], sq[4];
#pragma unroll
    for (int pp = 0; pp < 2; pp++) {
        float2 v0 = unpk(acc[0][pp]), v1 = unpk(acc[1][pp]);
        int o0 = 4 * tz + 2 * pp, o1 = o0 + 1;
        float2 lo = make_float2(v0.x, v1.x);
        float2 hi = make_float2(v0.y, v1.y);
        *reinterpret_cast<float2*>(&g_x2[((b * 8 + o0) * 128 + Y) * 128 + X]) = lo;
        *reinterpret_cast<float2*>(&g_x2[((b * 8 + o1) * 128 + Y) * 128 + X]) = hi;
        so[2 * pp]     = lo.x + lo.y;  sq[2 * pp]     = lo.x * lo.x + lo.y * lo.y;
        so[2 * pp + 1] = hi.x + hi.y;  sq[2 * pp + 1] = hi.x * hi.x + hi.y * hi.y;
    }
    int wid = tz * 4 + ty;
#pragma unroll
    for (int c = 0; c < 4; c++) {
        float s = so[c], q = sq[c];
#pragma unroll
        for (int d = 16; d > 0; d >>= 1) {
            s += __shfl_xor_sync(0xffffffffu, s, d);
            q += __shfl_xor_sync(0xffffffffu, q, d);
        }
        if (tx == 0) { rsum[wid][c] = s; rsq[wid][c] = q; }
    }
    __syncthreads();
    if (t < 8) {
        int grp = t >> 2;
        int cloc = t & 3;
        float S = 0.0f, Q = 0.0f;
#pragma unroll
        for (int wq = 0; wq < 4; wq++) { S += rsum[grp * 4 + wq][cloc]; Q += rsq[grp * 4 + wq][cloc]; }
        atomicAdd(&g_sum2[t], (double)S);
        atomicAdd(&g_sq2[t],  (double)Q);
    }
}

// ---------------- conv2 5x5 pad2 + relu, 2 X per thread + BN-final2 + sil (R8) ----------------
__global__ void k_conv2(const float* __restrict__ w2, const float* __restrict__ b2,
                        const float* __restrict__ g2, const float* __restrict__ be2,
                        float* __restrict__ out) {
    __shared__ __align__(16) ull wA[8 * 25];
    __shared__ float wB[8 * 25];
    __shared__ __align__(16) float tile[4][12][72];
    __shared__ float sa[8], sc[8];
    int tx = threadIdx.x, ty = threadIdx.y;
    int t = ty * 32 + tx;

    for (int j = t; j < 200; j += 256) {
        wA[j] = pk2(w2[j], w2[200 + j]);
        wB[j] = w2[400 + j];
    }
    if (t < 8) {
        double N = (double)(B_ * IMG_ * IMG_);
        double m = g_sum2[t] / N;
        double v = g_sq2[t] / N - m * m;
        float rs = rsqrtf((float)v + 1e-5f);
        float a = g2[t] * rs;
        sa[t] = a;
        sc[t] = be2[t] - (float)m * a;
    }

    int Xb = blockIdx.x * 64;
    int Y0 = blockIdx.y * 8, b = blockIdx.z;
    int Y = Y0 + ty;

    ull accp[2];
    float acc2[2];
    {
        ull iv = pk2(b2[0], b2[1]);
        accp[0] = iv; accp[1] = iv;
        acc2[0] = b2[2]; acc2[1] = b2[2];
    }

    for (int cc = 0; cc < 2; cc++) {
        __syncthreads();
        for (int j = t; j < 3456; j += 256) {
            int il = j / 864;
            int rem = j % 864;
            int r = rem / 72;
            int n = rem % 72;
            int yy = Y0 - 2 + r, xx = Xb - 2 + n;
            float v = 0.0f;
            if ((unsigned)yy < 128u && (unsigned)xx < 128u && n < 68) {
                int i = cc * 4 + il;
                float xv = g_x2[((b * 8 + i) * 128 + yy) * 128 + xx];
                xv = sa[i] * xv + sc[i];
                v = (xv >= 0.0f) ? xv : 0.01f * xv;
            }
            tile[il][r][n] = v;
        }
        __syncthreads();

#pragma unroll
        for (int il = 0; il < 4; il++) {
            int i = cc * 4 + il;
#pragma unroll
            for (int ky = 0; ky < 5; ky++) {
                const float2* rp = reinterpret_cast<const float2*>(&tile[il][ty + ky][tx * 2]);
                float2 a0 = rp[0], a1 = rp[1], a2 = rp[2];
                float w6[6] = {a0.x, a0.y, a1.x, a1.y, a2.x, a2.y};
                ull pw[6];
#pragma unroll
                for (int j2 = 0; j2 < 6; j2++) pw[j2] = pk2(w6[j2], w6[j2]);
#pragma unroll
                for (int kx = 0; kx < 5; kx++) {
                    ull wa = wA[i * 25 + ky * 5 + kx];
                    float wb = wB[i * 25 + ky * 5 + kx];
                    fma2(accp[0], wa, pw[kx]);
                    fma2(accp[1], wa, pw[kx + 1]);
                    acc2[0] = fmaf(w6[kx], wb, acc2[0]);
                    acc2[1] = fmaf(w6[kx + 1], wb, acc2[1]);
                }
            }
        }
    }

    int X = Xb + tx * 2;
    {
        float2 u0 = unpk(accp[0]), u1 = unpk(accp[1]);
        float2 o0v = make_float2(fmaxf(u0.x, 0.0f), fmaxf(u1.x, 0.0f));
        float2 o1v = make_float2(fmaxf(u0.y, 0.0f), fmaxf(u1.y, 0.0f));
        float2 o2v = make_float2(fmaxf(acc2[0], 0.0f), fmaxf(acc2[1], 0.0f));
        int base = ((b * 3) * 128 + Y) * 128 + X;
        *reinterpret_cast<float2*>(&out[base])             = o0v;
        *reinterpret_cast<float2*>(&out[base + 16384])     = o1v;
        *reinterpret_cast<float2*>(&out[base + 2 * 16384]) = o2v;
    }

    const float* op = g_opac + b * 4096;
    float sy = (float)Y * 0.5f - 0.25f;
    int y0 = (int)floorf(sy);
    float wy = sy - (float)y0;
    int y0c = max(y0, 0), y1c = min(y0 + 1, 63);
#pragma unroll
    for (int x = 0; x < 2; x++) {
        int Xx = X + x;
        float sx = (float)Xx * 0.5f - 0.25f;
        int x0 = (int)floorf(sx);
        float wx = sx - (float)x0;
        int x0c = max(x0, 0), x1c = min(x0 + 1, 63);
        float v = (1.0f - wy) * ((1.0f - wx) * op[y0c * 64 + x0c] + wx * op[y0c * 64 + x1c])
                +         wy  * ((1.0f - wx) * op[y1c * 64 + x0c] + wx * op[y1c * 64 + x1c]);
        out[B_ * 3 * IMG_ * IMG_ + (b << 14) + (Y << 7) + Xx] = v;
    }
}

// ---------------- launcher ----------------
extern "C" void kernel_launch(void* const* d_in, const int* in_sizes, int n_in,
                              void* d_out, int out_size) {
    const float* R   = (const float*)d_in[0];
    const float* T   = (const float*)d_in[1];
    const float* K   = (const float*)d_in[2];
    const float* f3  = (const float*)d_in[3];
    const float* dn  = (const float*)d_in[4];
    const float* wt  = (const float*)d_in[5];
    const float* bt  = (const float*)d_in[6];
    const float* g1  = (const float*)d_in[7];
    const float* be1 = (const float*)d_in[8];
    const float* w1  = (const float*)d_in[9];
    const float* b1  = (const float*)d_in[10];
    const float* g2  = (const float*)d_in[11];
    const float* be2 = (const float*)d_in[12];
    const float* w2  = (const float*)d_in[13];
    const float* b2  = (const float*)d_in[14];
    float* out = (float*)d_out;

    k_transpose<<<(B_ * D_ * D_ * D_ + 255) / 256, 256>>>(f3);
    k_render<<<(B_ * HW_ * HW_ * 8) / 128, 128>>>(R, T, K, dn);

    k_convt<<<dim3(2, 16, B_), dim3(32, 8)>>>(wt, bt);
    k_conv1<<<dim3(2, 32, B_), dim3(32, 4, 2)>>>(w1, b1, g1, be1);
    k_conv2<<<dim3(2, 16, B_), dim3(32, 8)>>>(w2, b2, g2, be2, out);
}

// round 14
// speedup vs baseline: 1.0854x; 1.0854x over previous
#include <cuda_runtime.h>
#include <cuda_fp16.h>
#include <math.h>

#define B_   8
#define C_   16
#define D_   64
#define HW_  64
#define NP_  64
#define IMG_ 128

typedef unsigned long long ull;

// ---------------- f32x2 helpers (sm_10x packed fp32 FMA) ----------------
__device__ __forceinline__ ull pk2(float x, float y) {
    ull r;
    asm("mov.b64 %0, {%1, %2};" : "=l"(r) : "f"(x), "f"(y));
    return r;
}
__device__ __forceinline__ void fma2(ull& d, ull a, ull b) {
    asm("fma.rn.f32x2 %0, %1, %2, %0;" : "+l"(d) : "l"(a), "l"(b));
}
__device__ __forceinline__ float2 unpk(ull v) {
    float2 r;
    asm("mov.b64 {%0, %1}, %2;" : "=f"(r.x), "=f"(r.y) : "l"(v));
    return r;
}

// ---------------- device scratch (static, allocation-free) ----------------
__device__ __align__(16) __half g_featT[(size_t)B_ * D_ * D_ * D_ * C_];
__device__ __align__(16) float  g_imgs[B_ * C_ * HW_ * HW_];
__device__ __align__(16) float  g_opac[B_ * HW_ * HW_];
__device__ __align__(16) float  g_x1[B_ * 16 * IMG_ * IMG_];
__device__ __align__(16) float  g_x2[B_ * 8  * IMG_ * IMG_];
__device__ double g_sum1[16], g_sq1[16];
__device__ double g_sum2[8],  g_sq2[8];

// ---------------- feature transpose: (B,16,D,D,D) -> (B,D^3,16) fp16; clears stats (R8) ----------------
__global__ void k_transpose(const float* __restrict__ f) {
    if (blockIdx.x == 0 && threadIdx.x < 16) {
        g_sum1[threadIdx.x] = 0.0; g_sq1[threadIdx.x] = 0.0;
        if (threadIdx.x < 8) { g_sum2[threadIdx.x] = 0.0; g_sq2[threadIdx.x] = 0.0; }
    }
    int idx = blockIdx.x * blockDim.x + threadIdx.x;
    if (idx >= B_ * D_ * D_ * D_) return;
    int b = idx >> 18;
    int v = idx & 262143;
    __align__(16) __half2 tmp[8];
#pragma unroll
    for (int c = 0; c < 8; c++) {
        float a = f[((size_t)(b * 16 + 2 * c)) * 262144 + v];
        float bb = f[((size_t)(b * 16 + 2 * c + 1)) * 262144 + v];
        tmp[c] = __floats2half2_rn(a, bb);
    }
    uint4* out = reinterpret_cast<uint4*>(g_featT + (size_t)idx * 16);
    out[0] = *reinterpret_cast<uint4*>(&tmp[0]);
    out[1] = *reinterpret_cast<uint4*>(&tmp[4]);
}

// ---------------- trilerp corner helper: clamped offsets, masked weights ----------------
__device__ __forceinline__ void make_corners(float ix, float iy, float iz,
                                             float* __restrict__ ws, int* __restrict__ off) {
    float xf = floorf(ix), yf = floorf(iy), zf = floorf(iz);
    float fx = ix - xf, fy = iy - yf, fz = iz - zf;
    int x0 = (int)xf, y0 = (int)yf, z0 = (int)zf;
    float wx[2] = {1.0f - fx, fx};
    float wy[2] = {1.0f - fy, fy};
    float wz[2] = {1.0f - fz, fz};
#pragma unroll
    for (int k = 0; k < 8; k++) {
        int dx = k & 1, dy = (k >> 1) & 1, dz = k >> 2;
        int xc = x0 + dx, yc = y0 + dy, zc = z0 + dz;
        bool v = ((unsigned)xc < 64u) && ((unsigned)yc < 64u) && ((unsigned)zc < 64u);
        ws[k] = v ? wx[dx] * wy[dy] * wz[dz] : 0.0f;
        int o = (zc * 64 + yc) * 64 + xc;
        off[k] = min(max(o, 0), 262143);
    }
}

__device__ __forceinline__ void acc_rec(float wk, uint4 r0, uint4 r1, float* __restrict__ acc) {
    float2 v;
    v = __half22float2(*reinterpret_cast<const __half2*>(&r0.x));
    acc[0]  = fmaf(wk, v.x, acc[0]);  acc[1]  = fmaf(wk, v.y, acc[1]);
    v = __half22float2(*reinterpret_cast<const __half2*>(&r0.y));
    acc[2]  = fmaf(wk, v.x, acc[2]);  acc[3]  = fmaf(wk, v.y, acc[3]);
    v = __half22float2(*reinterpret_cast<const __half2*>(&r0.z));
    acc[4]  = fmaf(wk, v.x, acc[4]);  acc[5]  = fmaf(wk, v.y, acc[5]);
    v = __half22float2(*reinterpret_cast<const __half2*>(&r0.w));
    acc[6]  = fmaf(wk, v.x, acc[6]);  acc[7]  = fmaf(wk, v.y, acc[7]);
    v = __half22float2(*reinterpret_cast<const __half2*>(&r1.x));
    acc[8]  = fmaf(wk, v.x, acc[8]);  acc[9]  = fmaf(wk, v.y, acc[9]);
    v = __half22float2(*reinterpret_cast<const __half2*>(&r1.y));
    acc[10] = fmaf(wk, v.x, acc[10]); acc[11] = fmaf(wk, v.y, acc[11]);
    v = __half22float2(*reinterpret_cast<const __half2*>(&r1.z));
    acc[12] = fmaf(wk, v.x, acc[12]); acc[13] = fmaf(wk, v.y, acc[13]);
    v = __half22float2(*reinterpret_cast<const __half2*>(&r1.w));
    acc[14] = fmaf(wk, v.x, acc[14]); acc[15] = fmaf(wk, v.y, acc[15]);
}

// ---------------- fused ray-march: 4 threads per pixel (R8 winner) ----------------
__global__ void k_render(const float* __restrict__ R, const float* __restrict__ T,
                         const float* __restrict__ K, const float* __restrict__ dens) {
    int gid = blockIdx.x * 128 + threadIdx.x;
    int seg = gid & 3;
    int pix = gid >> 2;
    int b = pix >> 12;
    int h = (pix >> 6) & 63;
    int w = pix & 63;

    const float* Rb = R + b * 9;
    const float* Kb = K + b * 9;
    const float* Tb = T + b * 3;

    float fxk = Kb[0] * 0.5f, cxk = Kb[2] * 0.5f;
    float fyk = Kb[4] * 0.5f, cyk = Kb[5] * 0.5f;
    float dcx = ((float)w + 0.5f - cxk) / fxk;
    float dcy = ((float)h + 0.5f - cyk) / fyk;

    float dwx = Rb[0] * dcx + Rb[3] * dcy + Rb[6];
    float dwy = Rb[1] * dcx + Rb[4] * dcy + Rb[7];
    float dwz = Rb[2] * dcx + Rb[5] * dcy + Rb[8];
    float ox = -(Rb[0] * Tb[0] + Rb[3] * Tb[1] + Rb[6] * Tb[2]);
    float oy = -(Rb[1] * Tb[0] + Rb[4] * Tb[1] + Rb[7] * Tb[2]);
    float oz = -(Rb[2] * Tb[0] + Rb[5] * Tb[1] + Rb[8] * Tb[2]);

    const float scale = 2.0f / ((1.0f / (float)D_) * (float)(D_ - 1));
    const float sgain = scale * 31.5f;
    const float dstep = (2.8f - 1.2f) / 63.0f;

    const float* db = dens + (size_t)b * 262144;
    const uint4* fb = reinterpret_cast<const uint4*>(g_featT) + (size_t)b * 262144 * 2;

    float Lea = 1.0f, Lpq = 1.0f;
#pragma unroll 4
    for (int j = 0; j < 16; j++) {
        int p = seg * 16 + j;
        float dpt = 1.2f + (float)p * dstep;
        float ix = fmaf(ox + dwx * dpt, sgain, 31.5f);
        float iy = fmaf(oy + dwy * dpt, sgain, 31.5f);
        float iz = fmaf(oz + dwz * dpt, sgain, 31.5f);
        float ws[8]; int off[8];
        make_corners(ix, iy, iz, ws, off);
        float d[8];
#pragma unroll
        for (int k = 0; k < 8; k++) d[k] = __ldg(&db[off[k]]);
        float s = 0.0f;
#pragma unroll
        for (int k = 0; k < 8; k++) s = fmaf(ws[k], d[k], s);
        Lea *= (1.0f + 1e-10f - s);
        Lpq *= (1.0f - s);
    }

    float ex = __shfl_up_sync(0xffffffffu, Lea, 1);
    ex = (seg == 0) ? 1.0f : ex;
    float u = __shfl_up_sync(0xffffffffu, ex, 1);
    if (seg >= 1) ex *= u;
    u = __shfl_up_sync(0xffffffffu, ex, 2);
    if (seg >= 2) ex *= u;
    float pq = Lpq;
    pq *= __shfl_xor_sync(0xffffffffu, pq, 1);
    pq *= __shfl_xor_sync(0xffffffffu, pq, 2);

    float acc[16];
#pragma unroll
    for (int c = 0; c < 16; c++) acc[c] = 0.0f;
    float Tcur = ex;
    for (int j = 0; j < 16; j++) {
        int p = seg * 16 + j;
        float dpt = 1.2f + (float)p * dstep;
        float ix = fmaf(ox + dwx * dpt, sgain, 31.5f);
        float iy = fmaf(oy + dwy * dpt, sgain, 31.5f);
        float iz = fmaf(oz + dwz * dpt, sgain, 31.5f);
        float ws[8]; int off[8];
        make_corners(ix, iy, iz, ws, off);
        float d[8];
#pragma unroll
        for (int k = 0; k < 8; k++) d[k] = __ldg(&db[off[k]]);
        float s = 0.0f;
#pragma unroll
        for (int k = 0; k < 8; k++) s = fmaf(ws[k], d[k], s);
        float wq = s * Tcur;
        Tcur *= (1.0f + 1e-10f - s);
        if (wq == 0.0f) continue;

        uint4 a0[4], a1[4];
#pragma unroll
        for (int k = 0; k < 4; k++) {
            const uint4* rec = fb + ((size_t)off[k] << 1);
            a0[k] = __ldg(rec);
            a1[k] = __ldg(rec + 1);
        }
#pragma unroll
        for (int k = 0; k < 4; k++) acc_rec(wq * ws[k], a0[k], a1[k], acc);
#pragma unroll
        for (int k = 0; k < 4; k++) {
            const uint4* rec = fb + ((size_t)off[k + 4] << 1);
            a0[k] = __ldg(rec);
            a1[k] = __ldg(rec + 1);
        }
#pragma unroll
        for (int k = 0; k < 4; k++) acc_rec(wq * ws[k + 4], a0[k], a1[k], acc);
    }

#pragma unroll
    for (int c = 0; c < 16; c++) {
        acc[c] += __shfl_xor_sync(0xffffffffu, acc[c], 1);
        acc[c] += __shfl_xor_sync(0xffffffffu, acc[c], 2);
    }
    if (seg == 0) {
#pragma unroll
        for (int c = 0; c < 16; c++)
            g_imgs[((b * 16 + c) << 12) + (h << 6) + w] = acc[c];
        g_opac[pix] = 1.0f - pq;
    }
}

// ---------------- transposed conv 6x6 s2: R5 geometry + oc-split tz (clean single-variable test) ----------------
// grid (2, 16, 8): blockIdx.x = X parity. block (32,8,2) = 512 threads, 4096 warps total.
// Thread: Xa = 4*tx+px, Xb = Xa+2, Y = Y0+ty, out-channels 8*tz..8*tz+7 (4 pairs).
__global__ void k_convt(const float* __restrict__ wt, const float* __restrict__ bt) {
    __shared__ __align__(16) ull swt[16 * 18 * 8];   // [(i*18 + ky*3+kxi)*8 + p]
    __shared__ __align__(16) float tile[8][7][68];
    __shared__ float rsum[16][8], rsq[16][8];        // [warp][local oc]
    int tx = threadIdx.x, ty = threadIdx.y, tz = threadIdx.z;
    int t = tz * 256 + ty * 32 + tx;
    int px = blockIdx.x;
    int kx0 = (px + 1) & 1;

    for (int j = t; j < 2304; j += 512) {
        int p = j & 7;
        int tap = (j >> 3) % 18;
        int i = j / 144;
        int ky = tap / 3, kxi = tap % 3;
        int kx = kx0 + 2 * kxi;
        int base = (i * 16 + 2 * p) * 36 + (5 - ky) * 6 + (5 - kx);
        swt[j] = pk2(wt[base], wt[base + 36]);
    }

    int Y0 = blockIdx.y * 8, b = blockIdx.z;
    int Y = Y0 + ty;
    int Xa = 4 * tx + px;
    int Xb = Xa + 2;
    int mb = (Y0 >> 1) - 2;
    int ky0 = (Y + 1) & 1;   // warp-uniform (ty fixed per warp)

    ull accA[4], accB[4];
#pragma unroll
    for (int pl = 0; pl < 4; pl++) {
        ull iv = pk2(bt[8 * tz + 2 * pl], bt[8 * tz + 2 * pl + 1]);
        accA[pl] = iv; accB[pl] = iv;
    }

    for (int cc = 0; cc < 2; cc++) {
        __syncthreads();
        for (int j = t; j < 3808; j += 512) {
            int il = j / 476;
            int rem = j % 476;
            int r = rem / 68;
            int n = rem % 68;
            int mm = mb + r, nn = n - 1;
            float v = 0.0f;
            if ((unsigned)mm < 64u && (unsigned)nn < 64u)
                v = g_imgs[((b * 16 + cc * 8 + il) * 64 + mm) * 64 + nn];
            tile[il][r][n] = v;
        }
        __syncthreads();

#pragma unroll
        for (int kk = 0; kk < 3; kk++) {
            int ky = ky0 + 2 * kk;
            int tr = ((Y + ky - 3) >> 1) - mb;
#pragma unroll
            for (int kxi = 0; kxi < 3; kxi++) {
                int kx = kx0 + 2 * kxi;
                int tca = ((Xa + kx - 3) >> 1) + 1;
#pragma unroll
                for (int il = 0; il < 8; il++) {
                    int i = cc * 8 + il;
                    float va = tile[il][tr][tca];
                    float vb = tile[il][tr][tca + 1];
                    ull pa = pk2(va, va), pb = pk2(vb, vb);
                    const ulonglong2* wp = reinterpret_cast<const ulonglong2*>(&swt[(i * 18 + ky * 3 + kxi) * 8 + 4 * tz]);
                    ulonglong2 q0 = wp[0], q1 = wp[1];
                    fma2(accA[0], q0.x, pa); fma2(accB[0], q0.x, pb);
                    fma2(accA[1], q0.y, pa); fma2(accB[1], q0.y, pb);
                    fma2(accA[2], q1.x, pa); fma2(accB[2], q1.x, pb);
                    fma2(accA[3], q1.y, pa); fma2(accB[3], q1.y, pb);
                }
            }
        }
    }

    float so[8], sq[8];
#pragma unroll
    for (int pl = 0; pl < 4; pl++) {
        float2 a = unpk(accA[pl]);
        float2 bb = unpk(accB[pl]);
        int o0 = 8 * tz + 2 * pl, o1 = o0 + 1;
        g_x1[((b * 16 + o0) * 128 + Y) * 128 + Xa] = a.x;
        g_x1[((b * 16 + o0) * 128 + Y) * 128 + Xb] = bb.x;
        g_x1[((b * 16 + o1) * 128 + Y) * 128 + Xa] = a.y;
        g_x1[((b * 16 + o1) * 128 + Y) * 128 + Xb] = bb.y;
        so[2 * pl]     = a.x + bb.x;  sq[2 * pl]     = a.x * a.x + bb.x * bb.x;
        so[2 * pl + 1] = a.y + bb.y;  sq[2 * pl + 1] = a.y * a.y + bb.y * bb.y;
    }
    int wid = tz * 8 + ty;
#pragma unroll
    for (int c = 0; c < 8; c++) {
        float s = so[c], q = sq[c];
#pragma unroll
        for (int d = 16; d > 0; d >>= 1) {
            s += __shfl_xor_sync(0xffffffffu, s, d);
            q += __shfl_xor_sync(0xffffffffu, q, d);
        }
        if (tx == 0) { rsum[wid][c] = s; rsq[wid][c] = q; }
    }
    __syncthreads();
    if (t < 16) {
        int grp = t >> 3;
        int cloc = t & 7;
        float S = 0.0f, Q = 0.0f;
#pragma unroll
        for (int wq = 0; wq < 8; wq++) { S += rsum[grp * 8 + wq][cloc]; Q += rsq[grp * 8 + wq][cloc]; }
        atomicAdd(&g_sum1[t], (double)S);
        atomicAdd(&g_sq1[t],  (double)Q);
    }
}

// ---------------- conv1 5x5 pad2: out-channel split, 512 CTAs x (32,4,2) (R8) ----------------
__global__ void k_conv1(const float* __restrict__ w1, const float* __restrict__ b1,
                        const float* __restrict__ g1, const float* __restrict__ be1) {
    __shared__ __align__(16) ull swp[16 * 25 * 4];
    __shared__ __align__(16) float tile[16][8][68];
    __shared__ float rsum[8][4], rsq[8][4];
    __shared__ float sa[16], sc[16];
    int tx = threadIdx.x, ty = threadIdx.y, tz = threadIdx.z;
    int t = tz * 128 + ty * 32 + tx;

    for (int j = t; j < 1600; j += 256) {
        int p = j & 3;
        int tap = (j >> 2) % 25;
        int i = j / 100;
        swp[(i * 25 + tap) * 4 + p] = pk2(w1[(2 * p) * 400 + i * 25 + tap],
                                          w1[(2 * p + 1) * 400 + i * 25 + tap]);
    }
    if (t < 16) {
        double N = (double)(B_ * IMG_ * IMG_);
        double m = g_sum1[t] / N;
        double v = g_sq1[t] / N - m * m;
        float rs = rsqrtf((float)v + 1e-5f);
        float a = g1[t] * rs;
        sa[t] = a;
        sc[t] = be1[t] - (float)m * a;
    }
    __syncthreads();

    int Xb = blockIdx.x * 64;
    int Y0 = blockIdx.y * 4, b = blockIdx.z;
    int Y = Y0 + ty;
    int X = Xb + 2 * tx;

    for (int j = t; j < 8704; j += 256) {
        int il = j / 544;
        int rem = j % 544;
        int r = rem / 68;
        int n = rem % 68;
        int yy = Y0 - 2 + r, xx = Xb - 2 + n;
        float v = 0.0f;
        if ((unsigned)yy < 128u && (unsigned)xx < 128u) {
            float xv = g_x1[((b * 16 + il) * 128 + yy) * 128 + xx];
            xv = sa[il] * xv + sc[il];
            v = (xv >= 0.0f) ? xv : 0.01f * xv;
        }
        tile[il][r][n] = v;
    }
    __syncthreads();

    ull acc[2][2];
    {
        ull iv0 = pk2(b1[4 * tz], b1[4 * tz + 1]);
        ull iv1 = pk2(b1[4 * tz + 2], b1[4 * tz + 3]);
        acc[0][0] = iv0; acc[1][0] = iv0;
        acc[0][1] = iv1; acc[1][1] = iv1;
    }

#pragma unroll
    for (int i = 0; i < 16; i++) {
#pragma unroll
        for (int ky = 0; ky < 5; ky++) {
            const float2* rp = reinterpret_cast<const float2*>(&tile[i][ty + ky][tx * 2]);
            float2 a0 = rp[0], a1 = rp[1], a2 = rp[2];
            float w6[6] = {a0.x, a0.y, a1.x, a1.y, a2.x, a2.y};
            ull pw[6];
#pragma unroll
            for (int j2 = 0; j2 < 6; j2++) pw[j2] = pk2(w6[j2], w6[j2]);
#pragma unroll
            for (int kx = 0; kx < 5; kx++) {
                const ulonglong2* wp = reinterpret_cast<const ulonglong2*>(&swp[(i * 25 + ky * 5 + kx) * 4 + 2 * tz]);
                ulonglong2 wv = *wp;
                ull v0 = pw[kx], v1 = pw[kx + 1];
                fma2(acc[0][0], wv.x, v0); fma2(acc[1][0], wv.x, v1);
                fma2(acc[0][1], wv.y, v0); fma2(acc[1][1], wv.y, v1);
            }
        }
    }

    float so[4], sq[4];
#pragma unroll
    for (int pp = 0; pp < 2; pp++) {
        float2 v0 = unpk(acc[0][pp]), v1 = unpk(acc[1][pp]);
        int o0 = 4 * tz + 2 * pp, o1 = o0 + 1;
        float2 lo = make_float2(v0.x, v1.x);
        float2 hi = make_float2(v0.y, v1.y);
        *reinterpret_cast<float2*>(&g_x2[((b * 8 + o0) * 128 + Y) * 128 + X]) = lo;
        *reinterpret_cast<float2*>(&g_x2[((b * 8 + o1) * 128 + Y) * 128 + X]) = hi;
        so[2 * pp]     = lo.x + lo.y;  sq[2 * pp]     = lo.x * lo.x + lo.y * lo.y;
        so[2 * pp + 1] = hi.x + hi.y;  sq[2 * pp + 1] = hi.x * hi.x + hi.y * hi.y;
    }
    int wid = tz * 4 + ty;
#pragma unroll
    for (int c = 0; c < 4; c++) {
        float s = so[c], q = sq[c];
#pragma unroll
        for (int d = 16; d > 0; d >>= 1) {
            s += __shfl_xor_sync(0xffffffffu, s, d);
            q += __shfl_xor_sync(0xffffffffu, q, d);
        }
        if (tx == 0) { rsum[wid][c] = s; rsq[wid][c] = q; }
    }
    __syncthreads();
    if (t < 8) {
        int grp = t >> 2;
        int cloc = t & 3;
        float S = 0.0f, Q = 0.0f;
#pragma unroll
        for (int wq = 0; wq < 4; wq++) { S += rsum[grp * 4 + wq][cloc]; Q += rsq[grp * 4 + wq][cloc]; }
        atomicAdd(&g_sum2[t], (double)S);
        atomicAdd(&g_sq2[t],  (double)Q);
    }
}

// ---------------- conv2 5x5 pad2 + relu, 2 X per thread + BN-final2 + sil (R8) ----------------
__global__ void k_conv2(const float* __restrict__ w2, const float* __restrict__ b2,
                        const float* __restrict__ g2, const float* __restrict__ be2,
                        float* __restrict__ out) {
    __shared__ __align__(16) ull wA[8 * 25];
    __shared__ float wB[8 * 25];
    __shared__ __align__(16) float tile[4][12][72];
    __shared__ float sa[8], sc[8];
    int tx = threadIdx.x, ty = threadIdx.y;
    int t = ty * 32 + tx;

    for (int j = t; j < 200; j += 256) {
        wA[j] = pk2(w2[j], w2[200 + j]);
        wB[j] = w2[400 + j];
    }
    if (t < 8) {
        double N = (double)(B_ * IMG_ * IMG_);
        double m = g_sum2[t] / N;
        double v = g_sq2[t] / N - m * m;
        float rs = rsqrtf((float)v + 1e-5f);
        float a = g2[t] * rs;
        sa[t] = a;
        sc[t] = be2[t] - (float)m * a;
    }

    int Xb = blockIdx.x * 64;
    int Y0 = blockIdx.y * 8, b = blockIdx.z;
    int Y = Y0 + ty;

    ull accp[2];
    float acc2[2];
    {
        ull iv = pk2(b2[0], b2[1]);
        accp[0] = iv; accp[1] = iv;
        acc2[0] = b2[2]; acc2[1] = b2[2];
    }

    for (int cc = 0; cc < 2; cc++) {
        __syncthreads();
        for (int j = t; j < 3456; j += 256) {
            int il = j / 864;
            int rem = j % 864;
            int r = rem / 72;
            int n = rem % 72;
            int yy = Y0 - 2 + r, xx = Xb - 2 + n;
            float v = 0.0f;
            if ((unsigned)yy < 128u && (unsigned)xx < 128u && n < 68) {
                int i = cc * 4 + il;
                float xv = g_x2[((b * 8 + i) * 128 + yy) * 128 + xx];
                xv = sa[i] * xv + sc[i];
                v = (xv >= 0.0f) ? xv : 0.01f * xv;
            }
            tile[il][r][n] = v;
        }
        __syncthreads();

#pragma unroll
        for (int il = 0; il < 4; il++) {
            int i = cc * 4 + il;
#pragma unroll
            for (int ky = 0; ky < 5; ky++) {
                const float2* rp = reinterpret_cast<const float2*>(&tile[il][ty + ky][tx * 2]);
                float2 a0 = rp[0], a1 = rp[1], a2 = rp[2];
                float w6[6] = {a0.x, a0.y, a1.x, a1.y, a2.x, a2.y};
                ull pw[6];
#pragma unroll
                for (int j2 = 0; j2 < 6; j2++) pw[j2] = pk2(w6[j2], w6[j2]);
#pragma unroll
                for (int kx = 0; kx < 5; kx++) {
                    ull wa = wA[i * 25 + ky * 5 + kx];
                    float wb = wB[i * 25 + ky * 5 + kx];
                    fma2(accp[0], wa, pw[kx]);
                    fma2(accp[1], wa, pw[kx + 1]);
                    acc2[0] = fmaf(w6[kx], wb, acc2[0]);
                    acc2[1] = fmaf(w6[kx + 1], wb, acc2[1]);
                }
            }
        }
    }

    int X = Xb + tx * 2;
    {
        float2 u0 = unpk(accp[0]), u1 = unpk(accp[1]);
        float2 o0v = make_float2(fmaxf(u0.x, 0.0f), fmaxf(u1.x, 0.0f));
        float2 o1v = make_float2(fmaxf(u0.y, 0.0f), fmaxf(u1.y, 0.0f));
        float2 o2v = make_float2(fmaxf(acc2[0], 0.0f), fmaxf(acc2[1], 0.0f));
        int base = ((b * 3) * 128 + Y) * 128 + X;
        *reinterpret_cast<float2*>(&out[base])             = o0v;
        *reinterpret_cast<float2*>(&out[base + 16384])     = o1v;
        *reinterpret_cast<float2*>(&out[base + 2 * 16384]) = o2v;
    }

    const float* op = g_opac + b * 4096;
    float sy = (float)Y * 0.5f - 0.25f;
    int y0 = (int)floorf(sy);
    float wy = sy - (float)y0;
    int y0c = max(y0, 0), y1c = min(y0 + 1, 63);
#pragma unroll
    for (int x = 0; x < 2; x++) {
        int Xx = X + x;
        float sx = (float)Xx * 0.5f - 0.25f;
        int x0 = (int)floorf(sx);
        float wx = sx - (float)x0;
        int x0c = max(x0, 0), x1c = min(x0 + 1, 63);
        float v = (1.0f - wy) * ((1.0f - wx) * op[y0c * 64 + x0c] + wx * op[y0c * 64 + x1c])
                +         wy  * ((1.0f - wx) * op[y1c * 64 + x0c] + wx * op[y1c * 64 + x1c]);
        out[B_ * 3 * IMG_ * IMG_ + (b << 14) + (Y << 7) + Xx] = v;
    }
}

// ---------------- launcher ----------------
extern "C" void kernel_launch(void* const* d_in, const int* in_sizes, int n_in,
                              void* d_out, int out_size) {
    const float* R   = (const float*)d_in[0];
    const float* T   = (const float*)d_in[1];
    const float* K   = (const float*)d_in[2];
    const float* f3  = (const float*)d_in[3];
    const float* dn  = (const float*)d_in[4];
    const float* wt  = (const float*)d_in[5];
    const float* bt  = (const float*)d_in[6];
    const float* g1  = (const float*)d_in[7];
    const float* be1 = (const float*)d_in[8];
    const float* w1  = (const float*)d_in[9];
    const float* b1  = (const float*)d_in[10];
    const float* g2  = (const float*)d_in[11];
    const float* be2 = (const float*)d_in[12];
    const float* w2  = (const float*)d_in[13];
    const float* b2  = (const float*)d_in[14];
    float* out = (float*)d_out;

    k_transpose<<<(B_ * D_ * D_ * D_ + 255) / 256, 256>>>(f3);
    k_render<<<(B_ * HW_ * HW_ * 4) / 128, 128>>>(R, T, K, dn);

    k_convt<<<dim3(2, 16, B_), dim3(32, 8, 2)>>>(wt, bt);
    k_conv1<<<dim3(2, 32, B_), dim3(32, 4, 2)>>>(w1, b1, g1, be1);
    k_conv2<<<dim3(2, 16, B_), dim3(32, 8)>>>(w2, b2, g2, be2, out);
}

// round 15
// speedup vs baseline: 1.0873x; 1.0017x over previous
#include <cuda_runtime.h>
#include <cuda_fp16.h>
#include <math.h>

#define B_   8
#define C_   16
#define D_   64
#define HW_  64
#define NP_  64
#define IMG_ 128

typedef unsigned long long ull;

// ---------------- f32x2 helpers (sm_10x packed fp32 FMA) ----------------
__device__ __forceinline__ ull pk2(float x, float y) {
    ull r;
    asm("mov.b64 %0, {%1, %2};" : "=l"(r) : "f"(x), "f"(y));
    return r;
}
__device__ __forceinline__ void fma2(ull& d, ull a, ull b) {
    asm("fma.rn.f32x2 %0, %1, %2, %0;" : "+l"(d) : "l"(a), "l"(b));
}
__device__ __forceinline__ float2 unpk(ull v) {
    float2 r;
    asm("mov.b64 {%0, %1}, %2;" : "=f"(r.x), "=f"(r.y) : "l"(v));
    return r;
}

// ---------------- device scratch (static, allocation-free) ----------------
__device__ __align__(16) __half g_featT[(size_t)B_ * D_ * D_ * D_ * C_];
__device__ __align__(16) float  g_imgs[B_ * C_ * HW_ * HW_];
__device__ __align__(16) float  g_opac[B_ * HW_ * HW_];
__device__ __align__(16) float  g_x1[B_ * 16 * IMG_ * IMG_];
__device__ __align__(16) float  g_x2[B_ * 8  * IMG_ * IMG_];
__device__ double g_sum1[16], g_sq1[16];
__device__ double g_sum2[8],  g_sq2[8];

// ---------------- feature transpose: (B,16,D,D,D) -> (B,D^3,16) fp16; clears stats ----------------
__global__ void k_transpose(const float* __restrict__ f) {
    if (blockIdx.x == 0 && threadIdx.x < 16) {
        g_sum1[threadIdx.x] = 0.0; g_sq1[threadIdx.x] = 0.0;
        if (threadIdx.x < 8) { g_sum2[threadIdx.x] = 0.0; g_sq2[threadIdx.x] = 0.0; }
    }
    int idx = blockIdx.x * blockDim.x + threadIdx.x;
    if (idx >= B_ * D_ * D_ * D_) return;
    int b = idx >> 18;
    int v = idx & 262143;
    __align__(16) __half2 tmp[8];
#pragma unroll
    for (int c = 0; c < 8; c++) {
        float a = f[((size_t)(b * 16 + 2 * c)) * 262144 + v];
        float bb = f[((size_t)(b * 16 + 2 * c + 1)) * 262144 + v];
        tmp[c] = __floats2half2_rn(a, bb);
    }
    uint4* out = reinterpret_cast<uint4*>(g_featT + (size_t)idx * 16);
    out[0] = *reinterpret_cast<uint4*>(&tmp[0]);
    out[1] = *reinterpret_cast<uint4*>(&tmp[4]);
}

// ---------------- trilerp corner helper: clamped offsets, masked weights ----------------
__device__ __forceinline__ void make_corners(float ix, float iy, float iz,
                                             float* __restrict__ ws, int* __restrict__ off) {
    float xf = floorf(ix), yf = floorf(iy), zf = floorf(iz);
    float fx = ix - xf, fy = iy - yf, fz = iz - zf;
    int x0 = (int)xf, y0 = (int)yf, z0 = (int)zf;
    float wx[2] = {1.0f - fx, fx};
    float wy[2] = {1.0f - fy, fy};
    float wz[2] = {1.0f - fz, fz};
#pragma unroll
    for (int k = 0; k < 8; k++) {
        int dx = k & 1, dy = (k >> 1) & 1, dz = k >> 2;
        int xc = x0 + dx, yc = y0 + dy, zc = z0 + dz;
        bool v = ((unsigned)xc < 64u) && ((unsigned)yc < 64u) && ((unsigned)zc < 64u);
        ws[k] = v ? wx[dx] * wy[dy] * wz[dz] : 0.0f;
        int o = (zc * 64 + yc) * 64 + xc;
        off[k] = min(max(o, 0), 262143);
    }
}

__device__ __forceinline__ void acc_rec(float wk, uint4 r0, uint4 r1, float* __restrict__ acc) {
    float2 v;
    v = __half22float2(*reinterpret_cast<const __half2*>(&r0.x));
    acc[0]  = fmaf(wk, v.x, acc[0]);  acc[1]  = fmaf(wk, v.y, acc[1]);
    v = __half22float2(*reinterpret_cast<const __half2*>(&r0.y));
    acc[2]  = fmaf(wk, v.x, acc[2]);  acc[3]  = fmaf(wk, v.y, acc[3]);
    v = __half22float2(*reinterpret_cast<const __half2*>(&r0.z));
    acc[4]  = fmaf(wk, v.x, acc[4]);  acc[5]  = fmaf(wk, v.y, acc[5]);
    v = __half22float2(*reinterpret_cast<const __half2*>(&r0.w));
    acc[6]  = fmaf(wk, v.x, acc[6]);  acc[7]  = fmaf(wk, v.y, acc[7]);
    v = __half22float2(*reinterpret_cast<const __half2*>(&r1.x));
    acc[8]  = fmaf(wk, v.x, acc[8]);  acc[9]  = fmaf(wk, v.y, acc[9]);
    v = __half22float2(*reinterpret_cast<const __half2*>(&r1.y));
    acc[10] = fmaf(wk, v.x, acc[10]); acc[11] = fmaf(wk, v.y, acc[11]);
    v = __half22float2(*reinterpret_cast<const __half2*>(&r1.z));
    acc[12] = fmaf(wk, v.x, acc[12]); acc[13] = fmaf(wk, v.y, acc[13]);
    v = __half22float2(*reinterpret_cast<const __half2*>(&r1.w));
    acc[14] = fmaf(wk, v.x, acc[14]); acc[15] = fmaf(wk, v.y, acc[15]);
}

// ---------------- fused ray-march: 4 threads per pixel ----------------
__global__ void k_render(const float* __restrict__ R, const float* __restrict__ T,
                         const float* __restrict__ K, const float* __restrict__ dens) {
    int gid = blockIdx.x * 128 + threadIdx.x;
    int seg = gid & 3;
    int pix = gid >> 2;
    int b = pix >> 12;
    int h = (pix >> 6) & 63;
    int w = pix & 63;

    const float* Rb = R + b * 9;
    const float* Kb = K + b * 9;
    const float* Tb = T + b * 3;

    float fxk = Kb[0] * 0.5f, cxk = Kb[2] * 0.5f;
    float fyk = Kb[4] * 0.5f, cyk = Kb[5] * 0.5f;
    float dcx = ((float)w + 0.5f - cxk) / fxk;
    float dcy = ((float)h + 0.5f - cyk) / fyk;

    float dwx = Rb[0] * dcx + Rb[3] * dcy + Rb[6];
    float dwy = Rb[1] * dcx + Rb[4] * dcy + Rb[7];
    float dwz = Rb[2] * dcx + Rb[5] * dcy + Rb[8];
    float ox = -(Rb[0] * Tb[0] + Rb[3] * Tb[1] + Rb[6] * Tb[2]);
    float oy = -(Rb[1] * Tb[0] + Rb[4] * Tb[1] + Rb[7] * Tb[2]);
    float oz = -(Rb[2] * Tb[0] + Rb[5] * Tb[1] + Rb[8] * Tb[2]);

    const float scale = 2.0f / ((1.0f / (float)D_) * (float)(D_ - 1));
    const float sgain = scale * 31.5f;
    const float dstep = (2.8f - 1.2f) / 63.0f;

    const float* db = dens + (size_t)b * 262144;
    const uint4* fb = reinterpret_cast<const uint4*>(g_featT) + (size_t)b * 262144 * 2;

    float Lea = 1.0f, Lpq = 1.0f;
#pragma unroll 4
    for (int j = 0; j < 16; j++) {
        int p = seg * 16 + j;
        float dpt = 1.2f + (float)p * dstep;
        float ix = fmaf(ox + dwx * dpt, sgain, 31.5f);
        float iy = fmaf(oy + dwy * dpt, sgain, 31.5f);
        float iz = fmaf(oz + dwz * dpt, sgain, 31.5f);
        float ws[8]; int off[8];
        make_corners(ix, iy, iz, ws, off);
        float d[8];
#pragma unroll
        for (int k = 0; k < 8; k++) d[k] = __ldg(&db[off[k]]);
        float s = 0.0f;
#pragma unroll
        for (int k = 0; k < 8; k++) s = fmaf(ws[k], d[k], s);
        Lea *= (1.0f + 1e-10f - s);
        Lpq *= (1.0f - s);
    }

    float ex = __shfl_up_sync(0xffffffffu, Lea, 1);
    ex = (seg == 0) ? 1.0f : ex;
    float u = __shfl_up_sync(0xffffffffu, ex, 1);
    if (seg >= 1) ex *= u;
    u = __shfl_up_sync(0xffffffffu, ex, 2);
    if (seg >= 2) ex *= u;
    float pq = Lpq;
    pq *= __shfl_xor_sync(0xffffffffu, pq, 1);
    pq *= __shfl_xor_sync(0xffffffffu, pq, 2);

    float acc[16];
#pragma unroll
    for (int c = 0; c < 16; c++) acc[c] = 0.0f;
    float Tcur = ex;
    for (int j = 0; j < 16; j++) {
        int p = seg * 16 + j;
        float dpt = 1.2f + (float)p * dstep;
        float ix = fmaf(ox + dwx * dpt, sgain, 31.5f);
        float iy = fmaf(oy + dwy * dpt, sgain, 31.5f);
        float iz = fmaf(oz + dwz * dpt, sgain, 31.5f);
        float ws[8]; int off[8];
        make_corners(ix, iy, iz, ws, off);
        float d[8];
#pragma unroll
        for (int k = 0; k < 8; k++) d[k] = __ldg(&db[off[k]]);
        float s = 0.0f;
#pragma unroll
        for (int k = 0; k < 8; k++) s = fmaf(ws[k], d[k], s);
        float wq = s * Tcur;
        Tcur *= (1.0f + 1e-10f - s);
        if (wq == 0.0f) continue;

        uint4 a0[4], a1[4];
#pragma unroll
        for (int k = 0; k < 4; k++) {
            const uint4* rec = fb + ((size_t)off[k] << 1);
            a0[k] = __ldg(rec);
            a1[k] = __ldg(rec + 1);
        }
#pragma unroll
        for (int k = 0; k < 4; k++) acc_rec(wq * ws[k], a0[k], a1[k], acc);
#pragma unroll
        for (int k = 0; k < 4; k++) {
            const uint4* rec = fb + ((size_t)off[k + 4] << 1);
            a0[k] = __ldg(rec);
            a1[k] = __ldg(rec + 1);
        }
#pragma unroll
        for (int k = 0; k < 4; k++) acc_rec(wq * ws[k + 4], a0[k], a1[k], acc);
    }

#pragma unroll
    for (int c = 0; c < 16; c++) {
        acc[c] += __shfl_xor_sync(0xffffffffu, acc[c], 1);
        acc[c] += __shfl_xor_sync(0xffffffffu, acc[c], 2);
    }
    if (seg == 0) {
#pragma unroll
        for (int c = 0; c < 16; c++)
            g_imgs[((b * 16 + c) << 12) + (h << 6) + w] = acc[c];
        g_opac[pix] = 1.0f - pq;
    }
}

// ---------------- transposed conv 6x6 s2, f32x2, 2 same-parity X per thread + BN1 stats ----------------
__global__ void k_convt(const float* __restrict__ wt, const float* __restrict__ bt) {
    __shared__ __align__(16) ull swt[16 * 18 * 8];
    __shared__ __align__(16) float tile[8][7][68];
    __shared__ float rsum[8][16], rsq[8][16];
    int tx = threadIdx.x, ty = threadIdx.y;
    int t = ty * 32 + tx;
    int px = blockIdx.x;
    int kx0 = (px + 1) & 1;

    for (int j = t; j < 2304; j += 256) {
        int p = j & 7;
        int tap = (j >> 3) % 18;
        int i = j / 144;
        int ky = tap / 3, kxi = tap % 3;
        int kx = kx0 + 2 * kxi;
        int base = (i * 16 + 2 * p) * 36 + (5 - ky) * 6 + (5 - kx);
        swt[j] = pk2(wt[base], wt[base + 36]);
    }

    int Y0 = blockIdx.y * 8, b = blockIdx.z;
    int Y = Y0 + ty;
    int Xa = 4 * tx + px;
    int Xb = Xa + 2;
    int mb = (Y0 >> 1) - 2;
    int ky0 = (Y + 1) & 1;

    ull accA[8], accB[8];
#pragma unroll
    for (int p = 0; p < 8; p++) {
        ull iv = pk2(bt[2 * p], bt[2 * p + 1]);
        accA[p] = iv; accB[p] = iv;
    }

    for (int cc = 0; cc < 2; cc++) {
        __syncthreads();
        for (int j = t; j < 3808; j += 256) {
            int il = j / 476;
            int rem = j % 476;
            int r = rem / 68;
            int n = rem % 68;
            int mm = mb + r, nn = n - 1;
            float v = 0.0f;
            if ((unsigned)mm < 64u && (unsigned)nn < 64u)
                v = g_imgs[((b * 16 + cc * 8 + il) * 64 + mm) * 64 + nn];
            tile[il][r][n] = v;
        }
        __syncthreads();

#pragma unroll
        for (int kk = 0; kk < 3; kk++) {
            int ky = ky0 + 2 * kk;
            int tr = ((Y + ky - 3) >> 1) - mb;
#pragma unroll
            for (int kxi = 0; kxi < 3; kxi++) {
                int kx = kx0 + 2 * kxi;
                int tca = ((Xa + kx - 3) >> 1) + 1;
#pragma unroll
                for (int il = 0; il < 8; il++) {
                    int i = cc * 8 + il;
                    float va = tile[il][tr][tca];
                    float vb = tile[il][tr][tca + 1];
                    ull pa = pk2(va, va), pb = pk2(vb, vb);
                    const ulonglong2* wp = reinterpret_cast<const ulonglong2*>(&swt[(i * 18 + ky * 3 + kxi) * 8]);
                    ulonglong2 q0 = wp[0], q1 = wp[1], q2 = wp[2], q3 = wp[3];
                    fma2(accA[0], q0.x, pa); fma2(accB[0], q0.x, pb);
                    fma2(accA[1], q0.y, pa); fma2(accB[1], q0.y, pb);
                    fma2(accA[2], q1.x, pa); fma2(accB[2], q1.x, pb);
                    fma2(accA[3], q1.y, pa); fma2(accB[3], q1.y, pb);
                    fma2(accA[4], q2.x, pa); fma2(accB[4], q2.x, pb);
                    fma2(accA[5], q2.y, pa); fma2(accB[5], q2.y, pb);
                    fma2(accA[6], q3.x, pa); fma2(accB[6], q3.x, pb);
                    fma2(accA[7], q3.y, pa); fma2(accB[7], q3.y, pb);
                }
            }
        }
    }

    float so[16], sq[16];
#pragma unroll
    for (int p = 0; p < 8; p++) {
        float2 a = unpk(accA[p]);
        float2 bb = unpk(accB[p]);
        int o0 = 2 * p, o1 = 2 * p + 1;
        g_x1[((b * 16 + o0) * 128 + Y) * 128 + Xa] = a.x;
        g_x1[((b * 16 + o0) * 128 + Y) * 128 + Xb] = bb.x;
        g_x1[((b * 16 + o1) * 128 + Y) * 128 + Xa] = a.y;
        g_x1[((b * 16 + o1) * 128 + Y) * 128 + Xb] = bb.y;
        so[o0] = a.x + bb.x;           sq[o0] = a.x * a.x + bb.x * bb.x;
        so[o1] = a.y + bb.y;           sq[o1] = a.y * a.y + bb.y * bb.y;
    }
#pragma unroll
    for (int c = 0; c < 16; c++) {
        float s = so[c], q = sq[c];
#pragma unroll
        for (int d = 16; d > 0; d >>= 1) {
            s += __shfl_xor_sync(0xffffffffu, s, d);
            q += __shfl_xor_sync(0xffffffffu, q, d);
        }
        if (tx == 0) { rsum[ty][c] = s; rsq[ty][c] = q; }
    }
    __syncthreads();
    if (t < 16) {
        float S = 0.0f, Q = 0.0f;
#pragma unroll
        for (int wq = 0; wq < 8; wq++) { S += rsum[wq][t]; Q += rsq[wq][t]; }
        atomicAdd(&g_sum1[t], (double)S);
        atomicAdd(&g_sq1[t],  (double)Q);
    }
}

// ---------------- conv1 5x5 pad2: out-channel split, 512 CTAs x (32,4,2) + BN-final1 + BN2 stats ----------------
__global__ void k_conv1(const float* __restrict__ w1, const float* __restrict__ b1,
                        const float* __restrict__ g1, const float* __restrict__ be1) {
    __shared__ __align__(16) ull swp[16 * 25 * 4];
    __shared__ __align__(16) float tile[16][8][68];
    __shared__ float rsum[8][4], rsq[8][4];
    __shared__ float sa[16], sc[16];
    int tx = threadIdx.x, ty = threadIdx.y, tz = threadIdx.z;
    int t = tz * 128 + ty * 32 + tx;

    for (int j = t; j < 1600; j += 256) {
        int p = j & 3;
        int tap = (j >> 2) % 25;
        int i = j / 100;
        swp[(i * 25 + tap) * 4 + p] = pk2(w1[(2 * p) * 400 + i * 25 + tap],
                                          w1[(2 * p + 1) * 400 + i * 25 + tap]);
    }
    if (t < 16) {
        double N = (double)(B_ * IMG_ * IMG_);
        double m = g_sum1[t] / N;
        double v = g_sq1[t] / N - m * m;
        float rs = rsqrtf((float)v + 1e-5f);
        float a = g1[t] * rs;
        sa[t] = a;
        sc[t] = be1[t] - (float)m * a;
    }
    __syncthreads();

    int Xb = blockIdx.x * 64;
    int Y0 = blockIdx.y * 4, b = blockIdx.z;
    int Y = Y0 + ty;
    int X = Xb + 2 * tx;

    for (int j = t; j < 8704; j += 256) {
        int il = j / 544;
        int rem = j % 544;
        int r = rem / 68;
        int n = rem % 68;
        int yy = Y0 - 2 + r, xx = Xb - 2 + n;
        float v = 0.0f;
        if ((unsigned)yy < 128u && (unsigned)xx < 128u) {
            float xv = g_x1[((b * 16 + il) * 128 + yy) * 128 + xx];
            xv = sa[il] * xv + sc[il];
            v = (xv >= 0.0f) ? xv : 0.01f * xv;
        }
        tile[il][r][n] = v;
    }
    __syncthreads();

    ull acc[2][2];
    {
        ull iv0 = pk2(b1[4 * tz], b1[4 * tz + 1]);
        ull iv1 = pk2(b1[4 * tz + 2], b1[4 * tz + 3]);
        acc[0][0] = iv0; acc[1][0] = iv0;
        acc[0][1] = iv1; acc[1][1] = iv1;
    }

#pragma unroll
    for (int i = 0; i < 16; i++) {
#pragma unroll
        for (int ky = 0; ky < 5; ky++) {
            const float2* rp = reinterpret_cast<const float2*>(&tile[i][ty + ky][tx * 2]);
            float2 a0 = rp[0], a1 = rp[1], a2 = rp[2];
            float w6[6] = {a0.x, a0.y, a1.x, a1.y, a2.x, a2.y};
            ull pw[6];
#pragma unroll
            for (int j2 = 0; j2 < 6; j2++) pw[j2] = pk2(w6[j2], w6[j2]);
#pragma unroll
            for (int kx = 0; kx < 5; kx++) {
                const ulonglong2* wp = reinterpret_cast<const ulonglong2*>(&swp[(i * 25 + ky * 5 + kx) * 4 + 2 * tz]);
                ulonglong2 wv = *wp;
                ull v0 = pw[kx], v1 = pw[kx + 1];
                fma2(acc[0][0], wv.x, v0); fma2(acc[1][0], wv.x, v1);
                fma2(acc[0][1], wv.y, v0); fma2(acc[1][1], wv.y, v1);
            }
        }
    }

    float so[4], sq[4];
#pragma unroll
    for (int pp = 0; pp < 2; pp++) {
        float2 v0 = unpk(acc[0][pp]), v1 = unpk(acc[1][pp]);
        int o0 = 4 * tz + 2 * pp, o1 = o0 + 1;
        float2 lo = make_float2(v0.x, v1.x);
        float2 hi = make_float2(v0.y, v1.y);
        *reinterpret_cast<float2*>(&g_x2[((b * 8 + o0) * 128 + Y) * 128 + X]) = lo;
        *reinterpret_cast<float2*>(&g_x2[((b * 8 + o1) * 128 + Y) * 128 + X]) = hi;
        so[2 * pp]     = lo.x + lo.y;  sq[2 * pp]     = lo.x * lo.x + lo.y * lo.y;
        so[2 * pp + 1] = hi.x + hi.y;  sq[2 * pp + 1] = hi.x * hi.x + hi.y * hi.y;
    }
    int wid = tz * 4 + ty;
#pragma unroll
    for (int c = 0; c < 4; c++) {
        float s = so[c], q = sq[c];
#pragma unroll
        for (int d = 16; d > 0; d >>= 1) {
            s += __shfl_xor_sync(0xffffffffu, s, d);
            q += __shfl_xor_sync(0xffffffffu, q, d);
        }
        if (tx == 0) { rsum[wid][c] = s; rsq[wid][c] = q; }
    }
    __syncthreads();
    if (t < 8) {
        int grp = t >> 2;
        int cloc = t & 3;
        float S = 0.0f, Q = 0.0f;
#pragma unroll
        for (int wq = 0; wq < 4; wq++) { S += rsum[grp * 4 + wq][cloc]; Q += rsq[grp * 4 + wq][cloc]; }
        atomicAdd(&g_sum2[t], (double)S);
        atomicAdd(&g_sq2[t],  (double)Q);
    }
}

// ---------------- conv2 5x5 pad2 + relu, 2 X per thread + BN-final2 + sil ----------------
__global__ void k_conv2(const float* __restrict__ w2, const float* __restrict__ b2,
                        const float* __restrict__ g2, const float* __restrict__ be2,
                        float* __restrict__ out) {
    __shared__ __align__(16) ull wA[8 * 25];
    __shared__ float wB[8 * 25];
    __shared__ __align__(16) float tile[4][12][72];
    __shared__ float sa[8], sc[8];
    int tx = threadIdx.x, ty = threadIdx.y;
    int t = ty * 32 + tx;

    for (int j = t; j < 200; j += 256) {
        wA[j] = pk2(w2[j], w2[200 + j]);
        wB[j] = w2[400 + j];
    }
    if (t < 8) {
        double N = (double)(B_ * IMG_ * IMG_);
        double m = g_sum2[t] / N;
        double v = g_sq2[t] / N - m * m;
        float rs = rsqrtf((float)v + 1e-5f);
        float a = g2[t] * rs;
        sa[t] = a;
        sc[t] = be2[t] - (float)m * a;
    }

    int Xb = blockIdx.x * 64;
    int Y0 = blockIdx.y * 8, b = blockIdx.z;
    int Y = Y0 + ty;

    ull accp[2];
    float acc2[2];
    {
        ull iv = pk2(b2[0], b2[1]);
        accp[0] = iv; accp[1] = iv;
        acc2[0] = b2[2]; acc2[1] = b2[2];
    }

    for (int cc = 0; cc < 2; cc++) {
        __syncthreads();
        for (int j = t; j < 3456; j += 256) {
            int il = j / 864;
            int rem = j % 864;
            int r = rem / 72;
            int n = rem % 72;
            int yy = Y0 - 2 + r, xx = Xb - 2 + n;
            float v = 0.0f;
            if ((unsigned)yy < 128u && (unsigned)xx < 128u && n < 68) {
                int i = cc * 4 + il;
                float xv = g_x2[((b * 8 + i) * 128 + yy) * 128 + xx];
                xv = sa[i] * xv + sc[i];
                v = (xv >= 0.0f) ? xv : 0.01f * xv;
            }
            tile[il][r][n] = v;
        }
        __syncthreads();

#pragma unroll
        for (int il = 0; il < 4; il++) {
            int i = cc * 4 + il;
#pragma unroll
            for (int ky = 0; ky < 5; ky++) {
                const float2* rp = reinterpret_cast<const float2*>(&tile[il][ty + ky][tx * 2]);
                float2 a0 = rp[0], a1 = rp[1], a2 = rp[2];
                float w6[6] = {a0.x, a0.y, a1.x, a1.y, a2.x, a2.y};
                ull pw[6];
#pragma unroll
                for (int j2 = 0; j2 < 6; j2++) pw[j2] = pk2(w6[j2], w6[j2]);
#pragma unroll
                for (int kx = 0; kx < 5; kx++) {
                    ull wa = wA[i * 25 + ky * 5 + kx];
                    float wb = wB[i * 25 + ky * 5 + kx];
                    fma2(accp[0], wa, pw[kx]);
                    fma2(accp[1], wa, pw[kx + 1]);
                    acc2[0] = fmaf(w6[kx], wb, acc2[0]);
                    acc2[1] = fmaf(w6[kx + 1], wb, acc2[1]);
                }
            }
        }
    }

    int X = Xb + tx * 2;
    {
        float2 u0 = unpk(accp[0]), u1 = unpk(accp[1]);
        float2 o0v = make_float2(fmaxf(u0.x, 0.0f), fmaxf(u1.x, 0.0f));
        float2 o1v = make_float2(fmaxf(u0.y, 0.0f), fmaxf(u1.y, 0.0f));
        float2 o2v = make_float2(fmaxf(acc2[0], 0.0f), fmaxf(acc2[1], 0.0f));
        int base = ((b * 3) * 128 + Y) * 128 + X;
        *reinterpret_cast<float2*>(&out[base])             = o0v;
        *reinterpret_cast<float2*>(&out[base + 16384])     = o1v;
        *reinterpret_cast<float2*>(&out[base + 2 * 16384]) = o2v;
    }

    const float* op = g_opac + b * 4096;
    float sy = (float)Y * 0.5f - 0.25f;
    int y0 = (int)floorf(sy);
    float wy = sy - (float)y0;
    int y0c = max(y0, 0), y1c = min(y0 + 1, 63);
#pragma unroll
    for (int x = 0; x < 2; x++) {
        int Xx = X + x;
        float sx = (float)Xx * 0.5f - 0.25f;
        int x0 = (int)floorf(sx);
        float wx = sx - (float)x0;
        int x0c = max(x0, 0), x1c = min(x0 + 1, 63);
        float v = (1.0f - wy) * ((1.0f - wx) * op[y0c * 64 + x0c] + wx * op[y0c * 64 + x1c])
                +         wy  * ((1.0f - wx) * op[y1c * 64 + x0c] + wx * op[y1c * 64 + x1c]);
        out[B_ * 3 * IMG_ * IMG_ + (b << 14) + (Y << 7) + Xx] = v;
    }
}

// ---------------- launcher ----------------
extern "C" void kernel_launch(void* const* d_in, const int* in_sizes, int n_in,
                              void* d_out, int out_size) {
    const float* R   = (const float*)d_in[0];
    const float* T   = (const float*)d_in[1];
    const float* K   = (const float*)d_in[2];
    const float* f3  = (const float*)d_in[3];
    const float* dn  = (const float*)d_in[4];
    const float* wt  = (const float*)d_in[5];
    const float* bt  = (const float*)d_in[6];
    const float* g1  = (const float*)d_in[7];
    const float* be1 = (const float*)d_in[8];
    const float* w1  = (const float*)d_in[9];
    const float* b1  = (const float*)d_in[10];
    const float* g2  = (const float*)d_in[11];
    const float* be2 = (const float*)d_in[12];
    const float* w2  = (const float*)d_in[13];
    const float* b2  = (const float*)d_in[14];
    float* out = (float*)d_out;

    k_transpose<<<(B_ * D_ * D_ * D_ + 255) / 256, 256>>>(f3);
    k_render<<<(B_ * HW_ * HW_ * 4) / 128, 128>>>(R, T, K, dn);

    k_convt<<<dim3(2, 16, B_), dim3(32, 8)>>>(wt, bt);
    k_conv1<<<dim3(2, 32, B_), dim3(32, 4, 2)>>>(w1, b1, g1, be1);
    k_conv2<<<dim3(2, 16, B_), dim3(32, 8)>>>(w2, b2, g2, be2, out);
}

// round 16
// speedup vs baseline: 1.1013x; 1.0129x over previous
#include <cuda_runtime.h>
#include <cuda_fp16.h>
#include <math.h>

#define B_   8
#define C_   16
#define D_   64
#define HW_  64
#define NP_  64
#define IMG_ 128

typedef unsigned long long ull;

// ---------------- f32x2 helpers (sm_10x packed fp32 FMA) ----------------
__device__ __forceinline__ ull pk2(float x, float y) {
    ull r;
    asm("mov.b64 %0, {%1, %2};" : "=l"(r) : "f"(x), "f"(y));
    return r;
}
__device__ __forceinline__ void fma2(ull& d, ull a, ull b) {
    asm("fma.rn.f32x2 %0, %1, %2, %0;" : "+l"(d) : "l"(a), "l"(b));
}
__device__ __forceinline__ float2 unpk(ull v) {
    float2 r;
    asm("mov.b64 {%0, %1}, %2;" : "=f"(r.x), "=f"(r.y) : "l"(v));
    return r;
}

// ---------------- device scratch (static, allocation-free) ----------------
__device__ __align__(16) __half g_featT[(size_t)B_ * D_ * D_ * D_ * C_];
__device__ __align__(16) float  g_imgs[B_ * C_ * HW_ * HW_];
__device__ __align__(16) float  g_opac[B_ * HW_ * HW_];
__device__ __align__(16) float  g_x1[B_ * 16 * IMG_ * IMG_];
__device__ __align__(16) float  g_x2[B_ * 8  * IMG_ * IMG_];
__device__ double g_sum1[16], g_sq1[16];
__device__ double g_sum2[8],  g_sq2[8];

// ---------------- feature transpose: (B,16,D,D,D) -> (B,D^3,16) fp16; clears stats ----------------
__global__ void k_transpose(const float* __restrict__ f) {
    if (blockIdx.x == 0 && threadIdx.x < 16) {
        g_sum1[threadIdx.x] = 0.0; g_sq1[threadIdx.x] = 0.0;
        if (threadIdx.x < 8) { g_sum2[threadIdx.x] = 0.0; g_sq2[threadIdx.x] = 0.0; }
    }
    int idx = blockIdx.x * blockDim.x + threadIdx.x;
    if (idx >= B_ * D_ * D_ * D_) return;
    int b = idx >> 18;
    int v = idx & 262143;
    __align__(16) __half2 tmp[8];
#pragma unroll
    for (int c = 0; c < 8; c++) {
        float a = f[((size_t)(b * 16 + 2 * c)) * 262144 + v];
        float bb = f[((size_t)(b * 16 + 2 * c + 1)) * 262144 + v];
        tmp[c] = __floats2half2_rn(a, bb);
    }
    uint4* out = reinterpret_cast<uint4*>(g_featT + (size_t)idx * 16);
    out[0] = *reinterpret_cast<uint4*>(&tmp[0]);
    out[1] = *reinterpret_cast<uint4*>(&tmp[4]);
}

// ---------------- trilerp corner helper: clamped offsets, masked weights ----------------
__device__ __forceinline__ void make_corners(float ix, float iy, float iz,
                                             float* __restrict__ ws, int* __restrict__ off) {
    float xf = floorf(ix), yf = floorf(iy), zf = floorf(iz);
    float fx = ix - xf, fy = iy - yf, fz = iz - zf;
    int x0 = (int)xf, y0 = (int)yf, z0 = (int)zf;
    float wx[2] = {1.0f - fx, fx};
    float wy[2] = {1.0f - fy, fy};
    float wz[2] = {1.0f - fz, fz};
#pragma unroll
    for (int k = 0; k < 8; k++) {
        int dx = k & 1, dy = (k >> 1) & 1, dz = k >> 2;
        int xc = x0 + dx, yc = y0 + dy, zc = z0 + dz;
        bool v = ((unsigned)xc < 64u) && ((unsigned)yc < 64u) && ((unsigned)zc < 64u);
        ws[k] = v ? wx[dx] * wy[dy] * wz[dz] : 0.0f;
        int o = (zc * 64 + yc) * 64 + xc;
        off[k] = min(max(o, 0), 262143);
    }
}

__device__ __forceinline__ void acc_rec(float wk, uint4 r0, uint4 r1, float* __restrict__ acc) {
    float2 v;
    v = __half22float2(*reinterpret_cast<const __half2*>(&r0.x));
    acc[0]  = fmaf(wk, v.x, acc[0]);  acc[1]  = fmaf(wk, v.y, acc[1]);
    v = __half22float2(*reinterpret_cast<const __half2*>(&r0.y));
    acc[2]  = fmaf(wk, v.x, acc[2]);  acc[3]  = fmaf(wk, v.y, acc[3]);
    v = __half22float2(*reinterpret_cast<const __half2*>(&r0.z));
    acc[4]  = fmaf(wk, v.x, acc[4]);  acc[5]  = fmaf(wk, v.y, acc[5]);
    v = __half22float2(*reinterpret_cast<const __half2*>(&r0.w));
    acc[6]  = fmaf(wk, v.x, acc[6]);  acc[7]  = fmaf(wk, v.y, acc[7]);
    v = __half22float2(*reinterpret_cast<const __half2*>(&r1.x));
    acc[8]  = fmaf(wk, v.x, acc[8]);  acc[9]  = fmaf(wk, v.y, acc[9]);
    v = __half22float2(*reinterpret_cast<const __half2*>(&r1.y));
    acc[10] = fmaf(wk, v.x, acc[10]); acc[11] = fmaf(wk, v.y, acc[11]);
    v = __half22float2(*reinterpret_cast<const __half2*>(&r1.z));
    acc[12] = fmaf(wk, v.x, acc[12]); acc[13] = fmaf(wk, v.y, acc[13]);
    v = __half22float2(*reinterpret_cast<const __half2*>(&r1.w));
    acc[14] = fmaf(wk, v.x, acc[14]); acc[15] = fmaf(wk, v.y, acc[15]);
}

// ---------------- fused ray-march: 4 threads per pixel + sigma-occupancy mask ----------------
__global__ void k_render(const float* __restrict__ R, const float* __restrict__ T,
                         const float* __restrict__ K, const float* __restrict__ dens) {
    int gid = blockIdx.x * 128 + threadIdx.x;
    int seg = gid & 3;
    int pix = gid >> 2;
    int b = pix >> 12;
    int h = (pix >> 6) & 63;
    int w = pix & 63;

    const float* Rb = R + b * 9;
    const float* Kb = K + b * 9;
    const float* Tb = T + b * 3;

    float fxk = Kb[0] * 0.5f, cxk = Kb[2] * 0.5f;
    float fyk = Kb[4] * 0.5f, cyk = Kb[5] * 0.5f;
    float dcx = ((float)w + 0.5f - cxk) / fxk;
    float dcy = ((float)h + 0.5f - cyk) / fyk;

    float dwx = Rb[0] * dcx + Rb[3] * dcy + Rb[6];
    float dwy = Rb[1] * dcx + Rb[4] * dcy + Rb[7];
    float dwz = Rb[2] * dcx + Rb[5] * dcy + Rb[8];
    float ox = -(Rb[0] * Tb[0] + Rb[3] * Tb[1] + Rb[6] * Tb[2]);
    float oy = -(Rb[1] * Tb[0] + Rb[4] * Tb[1] + Rb[7] * Tb[2]);
    float oz = -(Rb[2] * Tb[0] + Rb[5] * Tb[1] + Rb[8] * Tb[2]);

    const float scale = 2.0f / ((1.0f / (float)D_) * (float)(D_ - 1));
    const float sgain = scale * 31.5f;
    const float dstep = (2.8f - 1.2f) / 63.0f;

    const float* db = dens + (size_t)b * 262144;
    const uint4* fb = reinterpret_cast<const uint4*>(g_featT) + (size_t)b * 262144 * 2;

    // ---- Phase A: segment-local transmittance products + occupancy mask ----
    float Lea = 1.0f, Lpq = 1.0f;
    unsigned omask = 0u;
#pragma unroll 4
    for (int j = 0; j < 16; j++) {
        int p = seg * 16 + j;
        float dpt = 1.2f + (float)p * dstep;
        float ix = fmaf(ox + dwx * dpt, sgain, 31.5f);
        float iy = fmaf(oy + dwy * dpt, sgain, 31.5f);
        float iz = fmaf(oz + dwz * dpt, sgain, 31.5f);
        float ws[8]; int off[8];
        make_corners(ix, iy, iz, ws, off);
        float d[8];
#pragma unroll
        for (int k = 0; k < 8; k++) d[k] = __ldg(&db[off[k]]);
        float s = 0.0f;
#pragma unroll
        for (int k = 0; k < 8; k++) s = fmaf(ws[k], d[k], s);
        if (s != 0.0f) omask |= (1u << j);
        Lea *= (1.0f + 1e-10f - s);
        Lpq *= (1.0f - s);
    }

    // ---- Phase B: exclusive scan across the 4-lane group ----
    float ex = __shfl_up_sync(0xffffffffu, Lea, 1);
    ex = (seg == 0) ? 1.0f : ex;
    float u = __shfl_up_sync(0xffffffffu, ex, 1);
    if (seg >= 1) ex *= u;
    u = __shfl_up_sync(0xffffffffu, ex, 2);
    if (seg >= 2) ex *= u;
    float pq = Lpq;
    pq *= __shfl_xor_sync(0xffffffffu, pq, 1);
    pq *= __shfl_xor_sync(0xffffffffu, pq, 2);

    // ---- Phase C: weighted feature gathers (skip depths with sigma == 0) ----
    // NOTE: when s == 0, Tcur *= (1 + 1e-10 - 0) == Tcur in fp32 (1e-10 < ulp(1)/2),
    // and wq == 0 contributes nothing — skipping is bit-exact.
    float acc[16];
#pragma unroll
    for (int c = 0; c < 16; c++) acc[c] = 0.0f;
    float Tcur = ex;
    for (int j = 0; j < 16; j++) {
        if (!((omask >> j) & 1u)) continue;
        int p = seg * 16 + j;
        float dpt = 1.2f + (float)p * dstep;
        float ix = fmaf(ox + dwx * dpt, sgain, 31.5f);
        float iy = fmaf(oy + dwy * dpt, sgain, 31.5f);
        float iz = fmaf(oz + dwz * dpt, sgain, 31.5f);
        float ws[8]; int off[8];
        make_corners(ix, iy, iz, ws, off);
        float d[8];
#pragma unroll
        for (int k = 0; k < 8; k++) d[k] = __ldg(&db[off[k]]);
        float s = 0.0f;
#pragma unroll
        for (int k = 0; k < 8; k++) s = fmaf(ws[k], d[k], s);
        float wq = s * Tcur;
        Tcur *= (1.0f + 1e-10f - s);
        if (wq == 0.0f) continue;

        uint4 a0[4], a1[4];
#pragma unroll
        for (int k = 0; k < 4; k++) {
            const uint4* rec = fb + ((size_t)off[k] << 1);
            a0[k] = __ldg(rec);
            a1[k] = __ldg(rec + 1);
        }
#pragma unroll
        for (int k = 0; k < 4; k++) acc_rec(wq * ws[k], a0[k], a1[k], acc);
#pragma unroll
        for (int k = 0; k < 4; k++) {
            const uint4* rec = fb + ((size_t)off[k + 4] << 1);
            a0[k] = __ldg(rec);
            a1[k] = __ldg(rec + 1);
        }
#pragma unroll
        for (int k = 0; k < 4; k++) acc_rec(wq * ws[k + 4], a0[k], a1[k], acc);
    }

#pragma unroll
    for (int c = 0; c < 16; c++) {
        acc[c] += __shfl_xor_sync(0xffffffffu, acc[c], 1);
        acc[c] += __shfl_xor_sync(0xffffffffu, acc[c], 2);
    }
    if (seg == 0) {
#pragma unroll
        for (int c = 0; c < 16; c++)
            g_imgs[((b * 16 + c) << 12) + (h << 6) + w] = acc[c];
        g_opac[pix] = 1.0f - pq;
    }
}

// ---------------- transposed conv 6x6 s2, f32x2, 2 same-parity X per thread + BN1 stats ----------------
__global__ void k_convt(const float* __restrict__ wt, const float* __restrict__ bt) {
    __shared__ __align__(16) ull swt[16 * 18 * 8];
    __shared__ __align__(16) float tile[8][7][68];
    __shared__ float rsum[8][16], rsq[8][16];
    int tx = threadIdx.x, ty = threadIdx.y;
    int t = ty * 32 + tx;
    int px = blockIdx.x;
    int kx0 = (px + 1) & 1;

    for (int j = t; j < 2304; j += 256) {
        int p = j & 7;
        int tap = (j >> 3) % 18;
        int i = j / 144;
        int ky = tap / 3, kxi = tap % 3;
        int kx = kx0 + 2 * kxi;
        int base = (i * 16 + 2 * p) * 36 + (5 - ky) * 6 + (5 - kx);
        swt[j] = pk2(wt[base], wt[base + 36]);
    }

    int Y0 = blockIdx.y * 8, b = blockIdx.z;
    int Y = Y0 + ty;
    int Xa = 4 * tx + px;
    int Xb = Xa + 2;
    int mb = (Y0 >> 1) - 2;
    int ky0 = (Y + 1) & 1;

    ull accA[8], accB[8];
#pragma unroll
    for (int p = 0; p < 8; p++) {
        ull iv = pk2(bt[2 * p], bt[2 * p + 1]);
        accA[p] = iv; accB[p] = iv;
    }

    for (int cc = 0; cc < 2; cc++) {
        __syncthreads();
        for (int j = t; j < 3808; j += 256) {
            int il = j / 476;
            int rem = j % 476;
            int r = rem / 68;
            int n = rem % 68;
            int mm = mb + r, nn = n - 1;
            float v = 0.0f;
            if ((unsigned)mm < 64u && (unsigned)nn < 64u)
                v = g_imgs[((b * 16 + cc * 8 + il) * 64 + mm) * 64 + nn];
            tile[il][r][n] = v;
        }
        __syncthreads();

#pragma unroll
        for (int kk = 0; kk < 3; kk++) {
            int ky = ky0 + 2 * kk;
            int tr = ((Y + ky - 3) >> 1) - mb;
#pragma unroll
            for (int kxi = 0; kxi < 3; kxi++) {
                int kx = kx0 + 2 * kxi;
                int tca = ((Xa + kx - 3) >> 1) + 1;
#pragma unroll
                for (int il = 0; il < 8; il++) {
                    int i = cc * 8 + il;
                    float va = tile[il][tr][tca];
                    float vb = tile[il][tr][tca + 1];
                    ull pa = pk2(va, va), pb = pk2(vb, vb);
                    const ulonglong2* wp = reinterpret_cast<const ulonglong2*>(&swt[(i * 18 + ky * 3 + kxi) * 8]);
                    ulonglong2 q0 = wp[0], q1 = wp[1], q2 = wp[2], q3 = wp[3];
                    fma2(accA[0], q0.x, pa); fma2(accB[0], q0.x, pb);
                    fma2(accA[1], q0.y, pa); fma2(accB[1], q0.y, pb);
                    fma2(accA[2], q1.x, pa); fma2(accB[2], q1.x, pb);
                    fma2(accA[3], q1.y, pa); fma2(accB[3], q1.y, pb);
                    fma2(accA[4], q2.x, pa); fma2(accB[4], q2.x, pb);
                    fma2(accA[5], q2.y, pa); fma2(accB[5], q2.y, pb);
                    fma2(accA[6], q3.x, pa); fma2(accB[6], q3.x, pb);
                    fma2(accA[7], q3.y, pa); fma2(accB[7], q3.y, pb);
                }
            }
        }
    }

    float so[16], sq[16];
#pragma unroll
    for (int p = 0; p < 8; p++) {
        float2 a = unpk(accA[p]);
        float2 bb = unpk(accB[p]);
        int o0 = 2 * p, o1 = 2 * p + 1;
        g_x1[((b * 16 + o0) * 128 + Y) * 128 + Xa] = a.x;
        g_x1[((b * 16 + o0) * 128 + Y) * 128 + Xb] = bb.x;
        g_x1[((b * 16 + o1) * 128 + Y) * 128 + Xa] = a.y;
        g_x1[((b * 16 + o1) * 128 + Y) * 128 + Xb] = bb.y;
        so[o0] = a.x + bb.x;           sq[o0] = a.x * a.x + bb.x * bb.x;
        so[o1] = a.y + bb.y;           sq[o1] = a.y * a.y + bb.y * bb.y;
    }
#pragma unroll
    for (int c = 0; c < 16; c++) {
        float s = so[c], q = sq[c];
#pragma unroll
        for (int d = 16; d > 0; d >>= 1) {
            s += __shfl_xor_sync(0xffffffffu, s, d);
            q += __shfl_xor_sync(0xffffffffu, q, d);
        }
        if (tx == 0) { rsum[ty][c] = s; rsq[ty][c] = q; }
    }
    __syncthreads();
    if (t < 16) {
        float S = 0.0f, Q = 0.0f;
#pragma unroll
        for (int wq = 0; wq < 8; wq++) { S += rsum[wq][t]; Q += rsq[wq][t]; }
        atomicAdd(&g_sum1[t], (double)S);
        atomicAdd(&g_sq1[t],  (double)Q);
    }
}

// ---------------- conv1 5x5 pad2: out-channel split, 512 CTAs x (32,4,2) + BN-final1 + BN2 stats ----------------
__global__ void k_conv1(const float* __restrict__ w1, const float* __restrict__ b1,
                        const float* __restrict__ g1, const float* __restrict__ be1) {
    __shared__ __align__(16) ull swp[16 * 25 * 4];
    __shared__ __align__(16) float tile[16][8][68];
    __shared__ float rsum[8][4], rsq[8][4];
    __shared__ float sa[16], sc[16];
    int tx = threadIdx.x, ty = threadIdx.y, tz = threadIdx.z;
    int t = tz * 128 + ty * 32 + tx;

    for (int j = t; j < 1600; j += 256) {
        int p = j & 3;
        int tap = (j >> 2) % 25;
        int i = j / 100;
        swp[(i * 25 + tap) * 4 + p] = pk2(w1[(2 * p) * 400 + i * 25 + tap],
                                          w1[(2 * p + 1) * 400 + i * 25 + tap]);
    }
    if (t < 16) {
        double N = (double)(B_ * IMG_ * IMG_);
        double m = g_sum1[t] / N;
        double v = g_sq1[t] / N - m * m;
        float rs = rsqrtf((float)v + 1e-5f);
        float a = g1[t] * rs;
        sa[t] = a;
        sc[t] = be1[t] - (float)m * a;
    }
    __syncthreads();

    int Xb = blockIdx.x * 64;
    int Y0 = blockIdx.y * 4, b = blockIdx.z;
    int Y = Y0 + ty;
    int X = Xb + 2 * tx;

    for (int j = t; j < 8704; j += 256) {
        int il = j / 544;
        int rem = j % 544;
        int r = rem / 68;
        int n = rem % 68;
        int yy = Y0 - 2 + r, xx = Xb - 2 + n;
        float v = 0.0f;
        if ((unsigned)yy < 128u && (unsigned)xx < 128u) {
            float xv = g_x1[((b * 16 + il) * 128 + yy) * 128 + xx];
            xv = sa[il] * xv + sc[il];
            v = (xv >= 0.0f) ? xv : 0.01f * xv;
        }
        tile[il][r][n] = v;
    }
    __syncthreads();

    ull acc[2][2];
    {
        ull iv0 = pk2(b1[4 * tz], b1[4 * tz + 1]);
        ull iv1 = pk2(b1[4 * tz + 2], b1[4 * tz + 3]);
        acc[0][0] = iv0; acc[1][0] = iv0;
        acc[0][1] = iv1; acc[1][1] = iv1;
    }

#pragma unroll
    for (int i = 0; i < 16; i++) {
#pragma unroll
        for (int ky = 0; ky < 5; ky++) {
            const float2* rp = reinterpret_cast<const float2*>(&tile[i][ty + ky][tx * 2]);
            float2 a0 = rp[0], a1 = rp[1], a2 = rp[2];
            float w6[6] = {a0.x, a0.y, a1.x, a1.y, a2.x, a2.y};
            ull pw[6];
#pragma unroll
            for (int j2 = 0; j2 < 6; j2++) pw[j2] = pk2(w6[j2], w6[j2]);
#pragma unroll
            for (int kx = 0; kx < 5; kx++) {
                const ulonglong2* wp = reinterpret_cast<const ulonglong2*>(&swp[(i * 25 + ky * 5 + kx) * 4 + 2 * tz]);
                ulonglong2 wv = *wp;
                ull v0 = pw[kx], v1 = pw[kx + 1];
                fma2(acc[0][0], wv.x, v0); fma2(acc[1][0], wv.x, v1);
                fma2(acc[0][1], wv.y, v0); fma2(acc[1][1], wv.y, v1);
            }
        }
    }

    float so[4], sq[4];
#pragma unroll
    for (int pp = 0; pp < 2; pp++) {
        float2 v0 = unpk(acc[0][pp]), v1 = unpk(acc[1][pp]);
        int o0 = 4 * tz + 2 * pp, o1 = o0 + 1;
        float2 lo = make_float2(v0.x, v1.x);
        float2 hi = make_float2(v0.y, v1.y);
        *reinterpret_cast<float2*>(&g_x2[((b * 8 + o0) * 128 + Y) * 128 + X]) = lo;
        *reinterpret_cast<float2*>(&g_x2[((b * 8 + o1) * 128 + Y) * 128 + X]) = hi;
        so[2 * pp]     = lo.x + lo.y;  sq[2 * pp]     = lo.x * lo.x + lo.y * lo.y;
        so[2 * pp + 1] = hi.x + hi.y;  sq[2 * pp + 1] = hi.x * hi.x + hi.y * hi.y;
    }
    int wid = tz * 4 + ty;
#pragma unroll
    for (int c = 0; c < 4; c++) {
        float s = so[c], q = sq[c];
#pragma unroll
        for (int d = 16; d > 0; d >>= 1) {
            s += __shfl_xor_sync(0xffffffffu, s, d);
            q += __shfl_xor_sync(0xffffffffu, q, d);
        }
        if (tx == 0) { rsum[wid][c] = s; rsq[wid][c] = q; }
    }
    __syncthreads();
    if (t < 8) {
        int grp = t >> 2;
        int cloc = t & 3;
        float S = 0.0f, Q = 0.0f;
#pragma unroll
        for (int wq = 0; wq < 4; wq++) { S += rsum[grp * 4 + wq][cloc]; Q += rsq[grp * 4 + wq][cloc]; }
        atomicAdd(&g_sum2[t], (double)S);
        atomicAdd(&g_sq2[t],  (double)Q);
    }
}

// ---------------- conv2 5x5 pad2 + relu, 2 X per thread + BN-final2 + sil ----------------
__global__ void k_conv2(const float* __restrict__ w2, const float* __restrict__ b2,
                        const float* __restrict__ g2, const float* __restrict__ be2,
                        float* __restrict__ out) {
    __shared__ __align__(16) ull wA[8 * 25];
    __shared__ float wB[8 * 25];
    __shared__ __align__(16) float tile[4][12][72];
    __shared__ float sa[8], sc[8];
    int tx = threadIdx.x, ty = threadIdx.y;
    int t = ty * 32 + tx;

    for (int j = t; j < 200; j += 256) {
        wA[j] = pk2(w2[j], w2[200 + j]);
        wB[j] = w2[400 + j];
    }
    if (t < 8) {
        double N = (double)(B_ * IMG_ * IMG_);
        double m = g_sum2[t] / N;
        double v = g_sq2[t] / N - m * m;
        float rs = rsqrtf((float)v + 1e-5f);
        float a = g2[t] * rs;
        sa[t] = a;
        sc[t] = be2[t] - (float)m * a;
    }

    int Xb = blockIdx.x * 64;
    int Y0 = blockIdx.y * 8, b = blockIdx.z;
    int Y = Y0 + ty;

    ull accp[2];
    float acc2[2];
    {
        ull iv = pk2(b2[0], b2[1]);
        accp[0] = iv; accp[1] = iv;
        acc2[0] = b2[2]; acc2[1] = b2[2];
    }

    for (int cc = 0; cc < 2; cc++) {
        __syncthreads();
        for (int j = t; j < 3456; j += 256) {
            int il = j / 864;
            int rem = j % 864;
            int r = rem / 72;
            int n = rem % 72;
            int yy = Y0 - 2 + r, xx = Xb - 2 + n;
            float v = 0.0f;
            if ((unsigned)yy < 128u && (unsigned)xx < 128u && n < 68) {
                int i = cc * 4 + il;
                float xv = g_x2[((b * 8 + i) * 128 + yy) * 128 + xx];
                xv = sa[i] * xv + sc[i];
                v = (xv >= 0.0f) ? xv : 0.01f * xv;
            }
            tile[il][r][n] = v;
        }
        __syncthreads();

#pragma unroll
        for (int il = 0; il < 4; il++) {
            int i = cc * 4 + il;
#pragma unroll
            for (int ky = 0; ky < 5; ky++) {
                const float2* rp = reinterpret_cast<const float2*>(&tile[il][ty + ky][tx * 2]);
                float2 a0 = rp[0], a1 = rp[1], a2 = rp[2];
                float w6[6] = {a0.x, a0.y, a1.x, a1.y, a2.x, a2.y};
                ull pw[6];
#pragma unroll
                for (int j2 = 0; j2 < 6; j2++) pw[j2] = pk2(w6[j2], w6[j2]);
#pragma unroll
                for (int kx = 0; kx < 5; kx++) {
                    ull wa = wA[i * 25 + ky * 5 + kx];
                    float wb = wB[i * 25 + ky * 5 + kx];
                    fma2(accp[0], wa, pw[kx]);
                    fma2(accp[1], wa, pw[kx + 1]);
                    acc2[0] = fmaf(w6[kx], wb, acc2[0]);
                    acc2[1] = fmaf(w6[kx + 1], wb, acc2[1]);
                }
            }
        }
    }

    int X = Xb + tx * 2;
    {
        float2 u0 = unpk(accp[0]), u1 = unpk(accp[1]);
        float2 o0v = make_float2(fmaxf(u0.x, 0.0f), fmaxf(u1.x, 0.0f));
        float2 o1v = make_float2(fmaxf(u0.y, 0.0f), fmaxf(u1.y, 0.0f));
        float2 o2v = make_float2(fmaxf(acc2[0], 0.0f), fmaxf(acc2[1], 0.0f));
        int base = ((b * 3) * 128 + Y) * 128 + X;
        *reinterpret_cast<float2*>(&out[base])             = o0v;
        *reinterpret_cast<float2*>(&out[base + 16384])     = o1v;
        *reinterpret_cast<float2*>(&out[base + 2 * 16384]) = o2v;
    }

    const float* op = g_opac + b * 4096;
    float sy = (float)Y * 0.5f - 0.25f;
    int y0 = (int)floorf(sy);
    float wy = sy - (float)y0;
    int y0c = max(y0, 0), y1c = min(y0 + 1, 63);
#pragma unroll
    for (int x = 0; x < 2; x++) {
        int Xx = X + x;
        float sx = (float)Xx * 0.5f - 0.25f;
        int x0 = (int)floorf(sx);
        float wx = sx - (float)x0;
        int x0c = max(x0, 0), x1c = min(x0 + 1, 63);
        float v = (1.0f - wy) * ((1.0f - wx) * op[y0c * 64 + x0c] + wx * op[y0c * 64 + x1c])
                +         wy  * ((1.0f - wx) * op[y1c * 64 + x0c] + wx * op[y1c * 64 + x1c]);
        out[B_ * 3 * IMG_ * IMG_ + (b << 14) + (Y << 7) + Xx] = v;
    }
}

// ---------------- launcher ----------------
extern "C" void kernel_launch(void* const* d_in, const int* in_sizes, int n_in,
                              void* d_out, int out_size) {
    const float* R   = (const float*)d_in[0];
    const float* T   = (const float*)d_in[1];
    const float* K   = (const float*)d_in[2];
    const float* f3  = (const float*)d_in[3];
    const float* dn  = (const float*)d_in[4];
    const float* wt  = (const float*)d_in[5];
    const float* bt  = (const float*)d_in[6];
    const float* g1  = (const float*)d_in[7];
    const float* be1 = (const float*)d_in[8];
    const float* w1  = (const float*)d_in[9];
    const float* b1  = (const float*)d_in[10];
    const float* g2  = (const float*)d_in[11];
    const float* be2 = (const float*)d_in[12];
    const float* w2  = (const float*)d_in[13];
    const float* b2  = (const float*)d_in[14];
    float* out = (float*)d_out;

    k_transpose<<<(B_ * D_ * D_ * D_ + 255) / 256, 256>>>(f3);
    k_render<<<(B_ * HW_ * HW_ * 4) / 128, 128>>>(R, T, K, dn);

    k_convt<<<dim3(2, 16, B_), dim3(32, 8)>>>(wt, bt);
    k_conv1<<<dim3(2, 32, B_), dim3(32, 4, 2)>>>(w1, b1, g1, be1);
    k_conv2<<<dim3(2, 16, B_), dim3(32, 8)>>>(w2, b2, g2, be2, out);
}